// round 10
// baseline (speedup 1.0000x reference)
#include <cuda_runtime.h>
#include <cuda_bf16.h>
#include <cstdint>

#define S_LEN 4096
#define HID   2048
#define NH    8
#define DHD   256
#define KW    1024      // HID/2 words per row (packed bf16x2)
#define DKW   128       // DHD/2 words
#define SW    2048      // S_LEN/2 words

// ---------------------------------------------------------------------------
// Scratch (static device globals: allocation-free per harness rules)
// ---------------------------------------------------------------------------
__device__ float    g_q[S_LEN * HID];
__device__ float    g_k[S_LEN * DHD];
__device__ float    g_v[S_LEN * DHD];
__device__ uint32_t g_xH[S_LEN * KW],  g_xL[S_LEN * KW];
__device__ uint32_t g_qH[S_LEN * KW],  g_qL[S_LEN * KW];
__device__ uint32_t g_kH[S_LEN * DKW], g_kL[S_LEN * DKW];
__device__ uint32_t g_vtH[DHD * SW],   g_vtL[DHD * SW];    // V^T packed seq-pairs
__device__ uint32_t g_aH[S_LEN * KW],  g_aL[S_LEN * KW];
__device__ uint32_t g_wqH[HID * KW],  g_wqL[HID * KW];
__device__ uint32_t g_wkH[DHD * KW],  g_wkL[DHD * KW];
__device__ uint32_t g_wvH[DHD * KW],  g_wvL[DHD * KW];
__device__ uint32_t g_woH[HID * KW],  g_woL[HID * KW];

// ---------------------------------------------------------------------------
// helpers
// ---------------------------------------------------------------------------
__device__ __forceinline__ uint32_t smem_u32(const void* p) {
    uint32_t a;
    asm("{ .reg .u64 t; cvta.to.shared.u64 t, %1; cvt.u32.u64 %0, t; }"
        : "=r"(a) : "l"(p));
    return a;
}
__device__ __forceinline__ float bf16_rn_f32(float x) {
    return __bfloat162float(__float2bfloat16(x));
}
__device__ __forceinline__ uint32_t bf16pack(float lo_k, float hi_k) {
    uint32_t r;
    asm("cvt.rn.bf16x2.f32 %0, %1, %2;" : "=r"(r) : "f"(hi_k), "f"(lo_k));
    return r;
}
__device__ __forceinline__ void packpair(float a, float b, uint32_t& H, uint32_t& L) {
    H = bf16pack(a, b);
    L = bf16pack(a - bf16_rn_f32(a), b - bf16_rn_f32(b));
}
__device__ __forceinline__ void split_pack4(float4 v, uint32_t* h, uint32_t* l) {
    packpair(v.x, v.y, h[0], l[0]);
    packpair(v.z, v.w, h[1], l[1]);
}
__device__ __forceinline__ void ldsm_x4(uint32_t* r, uint32_t addr) {
    asm volatile("ldmatrix.sync.aligned.m8n8.x4.shared.b16 {%0,%1,%2,%3}, [%4];"
        : "=r"(r[0]), "=r"(r[1]), "=r"(r[2]), "=r"(r[3]) : "r"(addr));
}
#define MMA_BF16(c, a, b)                                                   \
    asm volatile("mma.sync.aligned.m16n8k16.row.col.f32.bf16.bf16.f32 "     \
        "{%0,%1,%2,%3}, {%4,%5,%6,%7}, {%8,%9}, {%0,%1,%2,%3};"             \
        : "+f"((c)[0]), "+f"((c)[1]), "+f"((c)[2]), "+f"((c)[3])            \
        : "r"((a)[0]), "r"((a)[1]), "r"((a)[2]), "r"((a)[3]),               \
          "r"((b)[0]), "r"((b)[1]))
#define CP16(sm, gm) \
    asm volatile("cp.async.cg.shared.global [%0], [%1], 16;" :: "r"(sm), "l"(gm))
#define CPCOMMIT() asm volatile("cp.async.commit_group;")
#define CPWAIT0()  asm volatile("cp.async.wait_group 0;")
#define CPWAIT1()  asm volatile("cp.async.wait_group 1;")

// ---------------------------------------------------------------------------
// split_rows: fp32 [rows][2*Kw] -> packed hi/lo u32 [rows][Kw]
// ---------------------------------------------------------------------------
__global__ void split_rows(const float* __restrict__ in,
                           uint32_t* __restrict__ oH, uint32_t* __restrict__ oL)
{
    const size_t t = (size_t)blockIdx.x * blockDim.x + threadIdx.x;
    const float* p = in + t * 8;
    uint32_t h[2], l[2], h2[2], l2[2];
    split_pack4(*(const float4*)p, h, l);
    split_pack4(*(const float4*)(p + 4), h2, l2);
    *(uint4*)&oH[t * 4] = make_uint4(h[0], h[1], h2[0], h2[1]);
    *(uint4*)&oL[t * 4] = make_uint4(l[0], l[1], l2[0], l2[1]);
}

// ---------------------------------------------------------------------------
// transpose_split: in [R][C] fp32 -> out hi/lo u32 [C][R/2] (pairs along R)
// ---------------------------------------------------------------------------
__global__ void transpose_split(const float* __restrict__ in,
                                uint32_t* __restrict__ oH, uint32_t* __restrict__ oL,
                                int R, int C)
{
    __shared__ float t[32][33];
    const int c0 = blockIdx.x * 32, r0 = blockIdx.y * 32;
    const int tx = threadIdx.x, ty = threadIdx.y;
    #pragma unroll
    for (int j = 0; j < 4; ++j)
        t[ty + 8 * j][tx] = in[(size_t)(r0 + ty + 8 * j) * C + c0 + tx];
    __syncthreads();
    const int Rw = R >> 1;
    #pragma unroll
    for (int j = 0; j < 2; ++j) {
        const int jj = ty + 8 * j;
        const float a = t[2 * jj][tx], b = t[2 * jj + 1][tx];
        uint32_t H, L;
        packpair(a, b, H, L);
        oH[(size_t)(c0 + tx) * Rw + (r0 >> 1) + jj] = H;
        oL[(size_t)(c0 + tx) * Rw + (r0 >> 1) + jj] = L;
    }
}

// ---------------------------------------------------------------------------
// rope_split
// ---------------------------------------------------------------------------
__global__ void rope_split(const float* __restrict__ q, const float* __restrict__ k,
                           const int* __restrict__ pos,
                           uint32_t* __restrict__ qH, uint32_t* __restrict__ qL,
                           uint32_t* __restrict__ kH, uint32_t* __restrict__ kL)
{
    const int s = blockIdx.x;
    const int j = threadIdx.x;
    const float p = (float)pos[s];
    const float ia = 1.0f / powf(10000.0f, (float)(2 * j)     * (1.0f / 128.0f));
    const float ib = 1.0f / powf(10000.0f, (float)(2 * j + 1) * (1.0f / 128.0f));
    float sa, ca, sb, cb;
    sincosf(p * ia, &sa, &ca);
    sincosf(p * ib, &sb, &cb);

    #pragma unroll
    for (int h = 0; h < NH; ++h) {
        const float* base = q + (size_t)s * HID + h * DHD;
        float2 x1 = *(const float2*)&base[2 * j];
        float2 x2 = *(const float2*)&base[128 + 2 * j];
        const size_t wb = (size_t)s * KW + h * DKW;
        uint32_t H, L;
        packpair(x1.x * ca - x2.x * sa, x1.y * cb - x2.y * sb, H, L);
        qH[wb + j] = H;      qL[wb + j] = L;
        packpair(x2.x * ca + x1.x * sa, x2.y * cb + x1.y * sb, H, L);
        qH[wb + 64 + j] = H; qL[wb + 64 + j] = L;
    }
    {
        const float* base = k + (size_t)s * DHD;
        float2 x1 = *(const float2*)&base[2 * j];
        float2 x2 = *(const float2*)&base[128 + 2 * j];
        const size_t wb = (size_t)s * DKW;
        uint32_t H, L;
        packpair(x1.x * ca - x2.x * sa, x1.y * cb - x2.y * sb, H, L);
        kH[wb + j] = H;      kL[wb + j] = L;
        packpair(x2.x * ca + x1.x * sa, x2.y * cb + x1.y * sb, H, L);
        kH[wb + 64 + j] = H; kL[wb + 64 + j] = L;
    }
}

// ---------------------------------------------------------------------------
// GEMM on pre-split inputs.  512 threads (16 warps, 4/SMSP), warp tile 32x32.
// CTA 128x128, chunk 16 words; cp.async double-buffer; ldmatrix; term-major.
// ---------------------------------------------------------------------------
#define GP 20
#define OAL_B 10240
#define OBH_B 20480
#define OBL_B 30720
#define BUFW  10240
#define GEMM_SMEM (2 * BUFW * 4)

__global__ __launch_bounds__(512, 1)
void gemm_presplit(const uint32_t* __restrict__ AH, const uint32_t* __restrict__ AL,
                   const uint32_t* __restrict__ BH, const uint32_t* __restrict__ BL,
                   float* __restrict__ C, int M, int N, int Kw)
{
    extern __shared__ uint32_t smu[];
    const uint32_t sb = smem_u32(smu);

    const int tid  = threadIdx.x;
    const int wid  = tid >> 5, lane = tid & 31;
    const int g    = lane >> 2, tig = lane & 3;
    const int l8   = lane & 7, lb3 = (lane >> 3) & 1, lb4 = (lane >> 4) & 1;
    const int wm   = (wid & 3) * 32;       // 4 m-warps
    const int wn   = (wid >> 2) * 32;      // 4 n-warps
    const int m0   = blockIdx.y * 128, n0 = blockIdx.x * 128;

    const int lr = tid >> 2;               // 0..127
    const int wc = (tid & 3) * 4;          // word col 0,4,8,12
    const uint32_t* gah = AH + (size_t)(m0 + lr) * Kw + wc;
    const uint32_t* gal = AL + (size_t)(m0 + lr) * Kw + wc;
    const uint32_t* gbh = BH + (size_t)(n0 + lr) * Kw + wc;
    const uint32_t* gbl = BL + (size_t)(n0 + lr) * Kw + wc;

#define GISSUE(ci, bufbyte) do {                                            \
        const uint32_t _b = sb + (bufbyte) + (lr * GP + wc) * 4;            \
        CP16(_b,         gah + (ci) * 16);                                  \
        CP16(_b + OAL_B, gal + (ci) * 16);                                  \
        CP16(_b + OBH_B, gbh + (ci) * 16);                                  \
        CP16(_b + OBL_B, gbl + (ci) * 16);                                  \
    } while (0)

    float c[8][4];
    #pragma unroll
    for (int i = 0; i < 8; ++i)
        #pragma unroll
        for (int j = 0; j < 4; ++j) c[i][j] = 0.f;

    const int nch = Kw / 16;
    GISSUE(0, 0);
    CPCOMMIT();

    for (int c0 = 0; c0 < nch; ++c0) {
        const uint32_t cb = (uint32_t)(c0 & 1) * (BUFW * 4);
        if (c0 + 1 < nch) {
            GISSUE(c0 + 1, (uint32_t)((c0 + 1) & 1) * (BUFW * 4));
            CPCOMMIT();
            CPWAIT1();
        } else {
            CPWAIT0();
        }
        __syncthreads();

        #pragma unroll
        for (int ks = 0; ks < 2; ++ks) {
            const int wb = ks * 8;
            uint32_t aH[2][4], aL[2][4], bH[2][4], bL[2][4];
            #pragma unroll
            for (int mt = 0; mt < 2; ++mt) {
                const uint32_t ro = (uint32_t)((wm + mt * 16 + l8 + lb3 * 8) * GP
                                               + wb + lb4 * 4) * 4;
                ldsm_x4(aH[mt], sb + cb + ro);
                ldsm_x4(aL[mt], sb + cb + OAL_B + ro);
            }
            #pragma unroll
            for (int p = 0; p < 2; ++p) {
                const uint32_t ro = (uint32_t)((wn + p * 16 + lb4 * 8 + l8) * GP
                                               + wb + lb3 * 4) * 4;
                ldsm_x4(bH[p], sb + cb + OBH_B + ro);
                ldsm_x4(bL[p], sb + cb + OBL_B + ro);
            }
            #pragma unroll
            for (int mt = 0; mt < 2; ++mt)
                #pragma unroll
                for (int nt = 0; nt < 4; ++nt)
                    MMA_BF16(c[mt * 4 + nt], aH[mt], &bH[nt >> 1][(nt & 1) * 2]);
            #pragma unroll
            for (int mt = 0; mt < 2; ++mt)
                #pragma unroll
                for (int nt = 0; nt < 4; ++nt)
                    MMA_BF16(c[mt * 4 + nt], aH[mt], &bL[nt >> 1][(nt & 1) * 2]);
            #pragma unroll
            for (int mt = 0; mt < 2; ++mt)
                #pragma unroll
                for (int nt = 0; nt < 4; ++nt)
                    MMA_BF16(c[mt * 4 + nt], aL[mt], &bH[nt >> 1][(nt & 1) * 2]);
        }
        __syncthreads();
    }
#undef GISSUE

    #pragma unroll
    for (int mt = 0; mt < 2; ++mt)
        #pragma unroll
        for (int nt = 0; nt < 4; ++nt) {
            const float* cc = c[mt * 4 + nt];
            const int row = m0 + wm + mt * 16 + g;
            const int col = n0 + wn + nt * 8 + 2 * tig;
            *(float2*)&C[(size_t)row * N + col]       = make_float2(cc[0], cc[1]);
            *(float2*)&C[(size_t)(row + 8) * N + col] = make_float2(cc[2], cc[3]);
        }
}

// ---------------------------------------------------------------------------
// Flash attention, 512 threads (16 warps, 4/SMSP).
// Phase A: 16 warps as 2m x 8n over 64x64 S.  Phase C: 4m x 4n over 64x256.
// ---------------------------------------------------------------------------
#define QP 132
#define VP 36
#define PP 68
#define OFF_QH 0
#define OFF_QL (OFF_QH + 64 * QP)
#define OFF_KH (OFF_QL + 64 * QP)
#define OFF_KL (OFF_KH + 64 * QP)
#define OFF_VTH (OFF_KL + 64 * QP)
#define OFF_VTL (OFF_VTH + 256 * VP)
#define OFF_PS  (OFF_VTL + 256 * VP)
#define OFF_M   (OFF_PS + 64 * PP)
#define OFF_L   (OFF_M + 64)
#define OFF_C   (OFF_L + 64)
#define FA3_SMEM ((OFF_C + 64) * 4)

__global__ __launch_bounds__(512, 1) void flash_mma_bf16(
    const uint32_t* __restrict__ Qh, const uint32_t* __restrict__ Ql,
    const uint32_t* __restrict__ Kh, const uint32_t* __restrict__ Kl,
    const uint32_t* __restrict__ VtH, const uint32_t* __restrict__ VtL,
    uint32_t* __restrict__ AHo, uint32_t* __restrict__ ALo)
{
    extern __shared__ uint32_t smu[];
    float* smf = (float*)smu;
    const uint32_t sb = smem_u32(smu);

    const int tid  = threadIdx.x;
    const int wid  = tid >> 5, lane = tid & 31;
    const int g    = lane >> 2, tig = lane & 3;
    const int l8   = lane & 7, lb3 = (lane >> 3) & 1, lb4 = (lane >> 4) & 1;
    const int h    = blockIdx.y;
    const int it   = gridDim.x - 1 - blockIdx.x;

    const int wqm = (wid & 1) * 32;        // QK^T: 2 m-warps x 8 n-warps
    const int wqn = (wid >> 1) * 8;
    const int wpm = (wid & 3) * 16;        // P*V: 4 m-warps x 4 n-warps (64 dims)
    const int wpn = (wid >> 2) * 64;

    const int lr = tid & 63, lq = (tid >> 6) * 16;   // Q/K loader
    const int vd = tid >> 1, vh = (tid & 1) * 16;     // V loader
    const int srow = tid >> 3, sseg = (tid & 7) * 8;  // softmax: 8 threads/row

    // ---- stage Q + init state ----
    {
        const uint32_t* sH = Qh + (size_t)(it * 64 + lr) * KW + h * DKW + lq;
        const uint32_t* sL = Ql + (size_t)(it * 64 + lr) * KW + h * DKW + lq;
        const int d = lr * QP + lq;
        #pragma unroll
        for (int i = 0; i < 4; ++i) {
            *(uint4*)&smu[OFF_QH + d + 4 * i] = *(const uint4*)(sH + 4 * i);
            *(uint4*)&smu[OFF_QL + d + 4 * i] = *(const uint4*)(sL + 4 * i);
        }
        if (tid < 64) { smf[OFF_M + tid] = -1e30f; smf[OFF_L + tid] = 0.f; }
    }

    float o[8][4];
    #pragma unroll
    for (int i = 0; i < 8; ++i)
        #pragma unroll
        for (int j = 0; j < 4; ++j) o[i][j] = 0.f;

    const int rowq0 = wqm + l8 + lb3 * 8;
    const int rowp  = wpm + l8 + lb3 * 8;
    // phase-A K fragment: lanes<16 read KH, lanes>=16 read KL (combined ldsm)
    const uint32_t kfrag_base = (lb4 ? OFF_KL : OFF_KH) * 4;
    const int rowk  = wqn + l8;

    for (int jt = 0; jt <= it; ++jt) {
        __syncthreads();

        // ---- stage K ----
        {
            const uint32_t* sH = Kh + (size_t)(jt * 64 + lr) * DKW + lq;
            const uint32_t* sL = Kl + (size_t)(jt * 64 + lr) * DKW + lq;
            const int d = lr * QP + lq;
            #pragma unroll
            for (int i = 0; i < 4; ++i) {
                *(uint4*)&smu[OFF_KH + d + 4 * i] = *(const uint4*)(sH + 4 * i);
                *(uint4*)&smu[OFF_KL + d + 4 * i] = *(const uint4*)(sL + 4 * i);
            }
        }
        // ---- stage VT (pre-split, pre-transposed) ----
        {
            const uint32_t* sH = VtH + (size_t)vd * SW + jt * 32 + vh;
            const uint32_t* sL = VtL + (size_t)vd * SW + jt * 32 + vh;
            const int d = vd * VP + vh;
            #pragma unroll
            for (int i = 0; i < 4; ++i) {
                *(uint4*)&smu[OFF_VTH + d + 4 * i] = *(const uint4*)(sH + 4 * i);
                *(uint4*)&smu[OFF_VTL + d + 4 * i] = *(const uint4*)(sL + 4 * i);
            }
        }
        __syncthreads();

        // ---- Phase A: S = Q K^T ----
        {
            float s[2][4];
            #pragma unroll
            for (int a = 0; a < 2; ++a)
                #pragma unroll
                for (int j = 0; j < 4; ++j) s[a][j] = 0.f;

            #pragma unroll 4
            for (int ks = 0; ks < 16; ++ks) {
                const int wb = ks * 8;
                uint32_t aH0[4], aH1[4], aL0[4], aL1[4], bHL[4];
                const uint32_t qo = (uint32_t)(rowq0 * QP + wb + lb4 * 4) * 4;
                ldsm_x4(aH0, sb + OFF_QH * 4 + qo);
                ldsm_x4(aH1, sb + OFF_QH * 4 + qo + 16 * QP * 4);
                ldsm_x4(aL0, sb + OFF_QL * 4 + qo);
                ldsm_x4(aL1, sb + OFF_QL * 4 + qo + 16 * QP * 4);
                ldsm_x4(bHL, sb + kfrag_base
                              + (uint32_t)(rowk * QP + wb + lb3 * 4) * 4);
                MMA_BF16(s[0], aH0, &bHL[0]); MMA_BF16(s[1], aH1, &bHL[0]);
                MMA_BF16(s[0], aH0, &bHL[2]); MMA_BF16(s[1], aH1, &bHL[2]);
                MMA_BF16(s[0], aL0, &bHL[0]); MMA_BF16(s[1], aL1, &bHL[0]);
            }
            #pragma unroll
            for (int mf = 0; mf < 2; ++mf) {
                const int row = wqm + mf * 16 + g;
                const int col = wqn + 2 * tig;
                *(float2*)&smf[OFF_PS + row * PP + col]       = make_float2(s[mf][0], s[mf][1]);
                *(float2*)&smf[OFF_PS + (row + 8) * PP + col] = make_float2(s[mf][2], s[mf][3]);
            }
        }
        __syncthreads();

        // ---- Phase B: online softmax (8 threads/row); pack P in place ----
        {
            const bool diag = (jt == it);
            float pv[8];
            float mx = -1e30f;
            #pragma unroll
            for (int c = 0; c < 8; ++c) {
                const int col = sseg + c;
                float val = smf[OFF_PS + srow * PP + col] * 0.0625f;
                if (diag && col > srow) val = -1e30f;
                pv[c] = val;
                mx = fmaxf(mx, val);
            }
            mx = fmaxf(mx, __shfl_xor_sync(0xffffffffu, mx, 1));
            mx = fmaxf(mx, __shfl_xor_sync(0xffffffffu, mx, 2));
            mx = fmaxf(mx, __shfl_xor_sync(0xffffffffu, mx, 4));
            const float m_old = smf[OFF_M + srow];
            const float m_new = fmaxf(m_old, mx);
            const float corr  = __expf(m_old - m_new);
            float lsum = 0.f;
            #pragma unroll
            for (int c = 0; c < 8; ++c) {
                pv[c] = __expf(pv[c] - m_new);
                lsum += pv[c];
            }
            lsum += __shfl_xor_sync(0xffffffffu, lsum, 1);
            lsum += __shfl_xor_sync(0xffffffffu, lsum, 2);
            lsum += __shfl_xor_sync(0xffffffffu, lsum, 4);
            if ((tid & 7) == 0) {
                smf[OFF_M + srow] = m_new;
                smf[OFF_L + srow] = smf[OFF_L + srow] * corr + lsum;
                smf[OFF_C + srow] = corr;
            }
            __syncwarp();
            const int wbse = OFF_PS + srow * PP + (tid & 7) * 4;
            #pragma unroll
            for (int i = 0; i < 4; ++i) {
                uint32_t H, L;
                packpair(pv[2 * i], pv[2 * i + 1], H, L);
                smu[wbse + i]      = H;
                smu[wbse + 32 + i] = L;
            }
        }
        __syncthreads();

        // ---- Phase C: acc = acc*corr + P @ V ----
        {
            const float c_lo = smf[OFF_C + wpm + g];
            const float c_hi = smf[OFF_C + wpm + g + 8];
            #pragma unroll
            for (int nf = 0; nf < 8; ++nf) {
                o[nf][0] *= c_lo; o[nf][1] *= c_lo;
                o[nf][2] *= c_hi; o[nf][3] *= c_hi;
            }
            #pragma unroll
            for (int ks = 0; ks < 4; ++ks) {
                const int wb = ks * 8;
                uint32_t pH[4], pL[4], vH[4][4], vL[4][4];
                const uint32_t po = (uint32_t)(rowp * PP + wb + lb4 * 4) * 4;
                ldsm_x4(pH, sb + OFF_PS * 4 + po);
                ldsm_x4(pL, sb + OFF_PS * 4 + po + 128);
                #pragma unroll
                for (int vg = 0; vg < 4; ++vg) {
                    const uint32_t vo = (uint32_t)(
                        (wpn + vg * 16 + lb4 * 8 + l8) * VP + wb + lb3 * 4) * 4;
                    ldsm_x4(vH[vg], sb + OFF_VTH * 4 + vo);
                    ldsm_x4(vL[vg], sb + OFF_VTL * 4 + vo);
                }
                #pragma unroll
                for (int vg = 0; vg < 4; ++vg) {
                    MMA_BF16(o[vg * 2],     pH, &vH[vg][0]);
                    MMA_BF16(o[vg * 2 + 1], pH, &vH[vg][2]);
                }
                #pragma unroll
                for (int vg = 0; vg < 4; ++vg) {
                    MMA_BF16(o[vg * 2],     pH, &vL[vg][0]);
                    MMA_BF16(o[vg * 2 + 1], pH, &vL[vg][2]);
                }
                #pragma unroll
                for (int vg = 0; vg < 4; ++vg) {
                    MMA_BF16(o[vg * 2],     pL, &vH[vg][0]);
                    MMA_BF16(o[vg * 2 + 1], pL, &vH[vg][2]);
                }
            }
        }
    }

    // ---- normalize and write packed attn ----
    __syncthreads();
    {
        const float inv_lo = 1.0f / smf[OFF_L + wpm + g];
        const float inv_hi = 1.0f / smf[OFF_L + wpm + g + 8];
        const size_t row_lo = (size_t)(it * 64 + wpm + g);
        const size_t row_hi = row_lo + 8;
        #pragma unroll
        for (int nf = 0; nf < 8; ++nf) {
            const int wcol = h * DKW + (wpn >> 1) + nf * 4 + tig;
            uint32_t H, L;
            packpair(o[nf][0] * inv_lo, o[nf][1] * inv_lo, H, L);
            AHo[row_lo * KW + wcol] = H;
            ALo[row_lo * KW + wcol] = L;
            packpair(o[nf][2] * inv_hi, o[nf][3] * inv_hi, H, L);
            AHo[row_hi * KW + wcol] = H;
            ALo[row_hi * KW + wcol] = L;
        }
    }
}

// ---------------------------------------------------------------------------
extern "C" void kernel_launch(void* const* d_in, const int* in_sizes, int n_in,
                              void* d_out, int out_size)
{
    const float* X   = (const float*)d_in[0];
    const int*   pos = (const int*)  d_in[1];
    const float* wq  = (const float*)d_in[2];
    const float* wk  = (const float*)d_in[3];
    const float* wv  = (const float*)d_in[4];
    const float* wo  = (const float*)d_in[5];
    float* out = (float*)d_out;

    float *q, *k, *v;
    uint32_t *xH, *xL, *qH, *qL, *kH, *kL, *vtH, *vtL, *aH, *aL;
    uint32_t *wqH, *wqL, *wkH, *wkL, *wvH, *wvL, *woH, *woL;
    cudaGetSymbolAddress((void**)&q,   g_q);
    cudaGetSymbolAddress((void**)&k,   g_k);
    cudaGetSymbolAddress((void**)&v,   g_v);
    cudaGetSymbolAddress((void**)&xH,  g_xH);  cudaGetSymbolAddress((void**)&xL,  g_xL);
    cudaGetSymbolAddress((void**)&qH,  g_qH);  cudaGetSymbolAddress((void**)&qL,  g_qL);
    cudaGetSymbolAddress((void**)&kH,  g_kH);  cudaGetSymbolAddress((void**)&kL,  g_kL);
    cudaGetSymbolAddress((void**)&vtH, g_vtH); cudaGetSymbolAddress((void**)&vtL, g_vtL);
    cudaGetSymbolAddress((void**)&aH,  g_aH);  cudaGetSymbolAddress((void**)&aL,  g_aL);
    cudaGetSymbolAddress((void**)&wqH, g_wqH); cudaGetSymbolAddress((void**)&wqL, g_wqL);
    cudaGetSymbolAddress((void**)&wkH, g_wkH); cudaGetSymbolAddress((void**)&wkL, g_wkL);
    cudaGetSymbolAddress((void**)&wvH, g_wvH); cudaGetSymbolAddress((void**)&wvL, g_wvL);
    cudaGetSymbolAddress((void**)&woH, g_woH); cudaGetSymbolAddress((void**)&woL, g_woL);

    cudaFuncSetAttribute(gemm_presplit,
                         cudaFuncAttributeMaxDynamicSharedMemorySize, GEMM_SMEM);
    cudaFuncSetAttribute(flash_mma_bf16,
                         cudaFuncAttributeMaxDynamicSharedMemorySize, FA3_SMEM);

    dim3 tb(32, 8);
    // launch order chosen so the big Q-projection GEMM is launch #4 (ncu window)
    transpose_split<<<dim3(HID / 32, HID / 32), tb>>>(wq, wqH, wqL, HID, HID);   // 1
    transpose_split<<<dim3(DHD / 32, HID / 32), tb>>>(wk, wkH, wkL, HID, DHD);   // 2
    split_rows<<<S_LEN * KW / (256 * 4), 256>>>(X, xH, xL);                      // 3
    gemm_presplit<<<dim3(HID / 128, S_LEN / 128), 512, GEMM_SMEM>>>(             // 4
        xH, xL, wqH, wqL, q, S_LEN, HID, KW);
    transpose_split<<<dim3(DHD / 32, HID / 32), tb>>>(wv, wvH, wvL, HID, DHD);   // 5
    gemm_presplit<<<dim3(DHD / 128, S_LEN / 128), 512, GEMM_SMEM>>>(             // 6
        xH, xL, wkH, wkL, k, S_LEN, DHD, KW);
    gemm_presplit<<<dim3(DHD / 128, S_LEN / 128), 512, GEMM_SMEM>>>(             // 7
        xH, xL, wvH, wvL, v, S_LEN, DHD, KW);
    rope_split<<<S_LEN, 64>>>(q, k, pos, qH, qL, kH, kL);                        // 8
    transpose_split<<<dim3(HID / 32, HID / 32), tb>>>(wo, woH, woL, HID, HID);   // 9
    transpose_split<<<dim3(DHD / 32, S_LEN / 32), tb>>>(v, vtH, vtL, S_LEN, DHD);// 10
    flash_mma_bf16<<<dim3(S_LEN / 64, NH), 512, FA3_SMEM>>>(                     // 11
        qH, qL, kH, kL, vtH, vtL, aH, aL);
    gemm_presplit<<<dim3(HID / 128, S_LEN / 128), 512, GEMM_SMEM>>>(             // 12
        aH, aL, woH, woL, out, S_LEN, HID, KW);
}

// round 14
// speedup vs baseline: 1.0304x; 1.0304x over previous
#include <cuda_runtime.h>
#include <cuda_bf16.h>
#include <cstdint>

#define S_LEN 4096
#define HID   2048
#define NH    8
#define DHD   256
#define KW    1024      // HID/2 words per row (packed bf16x2)
#define DKW   128       // DHD/2 words
#define SW    2048      // S_LEN/2 words

// ---------------------------------------------------------------------------
// Scratch (static device globals: allocation-free per harness rules)
// ---------------------------------------------------------------------------
__device__ float    g_q[S_LEN * HID];
__device__ float    g_k[S_LEN * DHD];
__device__ float    g_v[S_LEN * DHD];
__device__ uint32_t g_xH[S_LEN * KW],  g_xL[S_LEN * KW];
__device__ uint32_t g_qH[S_LEN * KW],  g_qL[S_LEN * KW];
__device__ uint32_t g_kH[S_LEN * DKW], g_kL[S_LEN * DKW];
__device__ uint32_t g_vtH[DHD * SW],   g_vtL[DHD * SW];
__device__ uint32_t g_aH[S_LEN * KW],  g_aL[S_LEN * KW];
__device__ uint32_t g_wqH[HID * KW],  g_wqL[HID * KW];
__device__ uint32_t g_wkH[DHD * KW],  g_wkL[DHD * KW];
__device__ uint32_t g_wvH[DHD * KW],  g_wvL[DHD * KW];
__device__ uint32_t g_woH[HID * KW],  g_woL[HID * KW];

// ---------------------------------------------------------------------------
// helpers
// ---------------------------------------------------------------------------
__device__ __forceinline__ uint32_t smem_u32(const void* p) {
    uint32_t a;
    asm("{ .reg .u64 t; cvta.to.shared.u64 t, %1; cvt.u32.u64 %0, t; }"
        : "=r"(a) : "l"(p));
    return a;
}
__device__ __forceinline__ float bf16_rn_f32(float x) {
    return __bfloat162float(__float2bfloat16(x));
}
__device__ __forceinline__ uint32_t bf16pack(float lo_k, float hi_k) {
    uint32_t r;
    asm("cvt.rn.bf16x2.f32 %0, %1, %2;" : "=r"(r) : "f"(hi_k), "f"(lo_k));
    return r;
}
__device__ __forceinline__ void packpair(float a, float b, uint32_t& H, uint32_t& L) {
    H = bf16pack(a, b);
    L = bf16pack(a - bf16_rn_f32(a), b - bf16_rn_f32(b));
}
__device__ __forceinline__ void split_pack4(float4 v, uint32_t* h, uint32_t* l) {
    packpair(v.x, v.y, h[0], l[0]);
    packpair(v.z, v.w, h[1], l[1]);
}
__device__ __forceinline__ void ldsm_x4(uint32_t* r, uint32_t addr) {
    asm volatile("ldmatrix.sync.aligned.m8n8.x4.shared.b16 {%0,%1,%2,%3}, [%4];"
        : "=r"(r[0]), "=r"(r[1]), "=r"(r[2]), "=r"(r[3]) : "r"(addr));
}
#define MMA_BF16(c, a, b)                                                   \
    asm volatile("mma.sync.aligned.m16n8k16.row.col.f32.bf16.bf16.f32 "     \
        "{%0,%1,%2,%3}, {%4,%5,%6,%7}, {%8,%9}, {%0,%1,%2,%3};"             \
        : "+f"((c)[0]), "+f"((c)[1]), "+f"((c)[2]), "+f"((c)[3])            \
        : "r"((a)[0]), "r"((a)[1]), "r"((a)[2]), "r"((a)[3]),               \
          "r"((b)[0]), "r"((b)[1]))
#define CP16(sm, gm) \
    asm volatile("cp.async.cg.shared.global [%0], [%1], 16;" :: "r"(sm), "l"(gm))
#define CPCOMMIT() asm volatile("cp.async.commit_group;")
#define CPWAIT0()  asm volatile("cp.async.wait_group 0;")
#define CPWAIT1()  asm volatile("cp.async.wait_group 1;")

// ---------------------------------------------------------------------------
// split_rows: fp32 [rows][2*Kw] -> packed hi/lo u32 [rows][Kw]
// ---------------------------------------------------------------------------
__global__ void split_rows(const float* __restrict__ in,
                           uint32_t* __restrict__ oH, uint32_t* __restrict__ oL)
{
    const size_t t = (size_t)blockIdx.x * blockDim.x + threadIdx.x;
    const float* p = in + t * 8;
    uint32_t h[2], l[2], h2[2], l2[2];
    split_pack4(*(const float4*)p, h, l);
    split_pack4(*(const float4*)(p + 4), h2, l2);
    *(uint4*)&oH[t * 4] = make_uint4(h[0], h[1], h2[0], h2[1]);
    *(uint4*)&oL[t * 4] = make_uint4(l[0], l[1], l2[0], l2[1]);
}

// ---------------------------------------------------------------------------
// transpose_split: in [R][C] fp32 -> out hi/lo u32 [C][R/2]
// ---------------------------------------------------------------------------
__global__ void transpose_split(const float* __restrict__ in,
                                uint32_t* __restrict__ oH, uint32_t* __restrict__ oL,
                                int R, int C)
{
    __shared__ float t[32][33];
    const int c0 = blockIdx.x * 32, r0 = blockIdx.y * 32;
    const int tx = threadIdx.x, ty = threadIdx.y;
    #pragma unroll
    for (int j = 0; j < 4; ++j)
        t[ty + 8 * j][tx] = in[(size_t)(r0 + ty + 8 * j) * C + c0 + tx];
    __syncthreads();
    const int Rw = R >> 1;
    #pragma unroll
    for (int j = 0; j < 2; ++j) {
        const int jj = ty + 8 * j;
        const float a = t[2 * jj][tx], b = t[2 * jj + 1][tx];
        uint32_t H, L;
        packpair(a, b, H, L);
        oH[(size_t)(c0 + tx) * Rw + (r0 >> 1) + jj] = H;
        oL[(size_t)(c0 + tx) * Rw + (r0 >> 1) + jj] = L;
    }
}

// ---------------------------------------------------------------------------
// rope_split
// ---------------------------------------------------------------------------
__global__ void rope_split(const float* __restrict__ q, const float* __restrict__ k,
                           const int* __restrict__ pos,
                           uint32_t* __restrict__ qH, uint32_t* __restrict__ qL,
                           uint32_t* __restrict__ kH, uint32_t* __restrict__ kL)
{
    const int s = blockIdx.x;
    const int j = threadIdx.x;
    const float p = (float)pos[s];
    const float ia = 1.0f / powf(10000.0f, (float)(2 * j)     * (1.0f / 128.0f));
    const float ib = 1.0f / powf(10000.0f, (float)(2 * j + 1) * (1.0f / 128.0f));
    float sa, ca, sb, cb;
    sincosf(p * ia, &sa, &ca);
    sincosf(p * ib, &sb, &cb);

    #pragma unroll
    for (int h = 0; h < NH; ++h) {
        const float* base = q + (size_t)s * HID + h * DHD;
        float2 x1 = *(const float2*)&base[2 * j];
        float2 x2 = *(const float2*)&base[128 + 2 * j];
        const size_t wb = (size_t)s * KW + h * DKW;
        uint32_t H, L;
        packpair(x1.x * ca - x2.x * sa, x1.y * cb - x2.y * sb, H, L);
        qH[wb + j] = H;      qL[wb + j] = L;
        packpair(x2.x * ca + x1.x * sa, x2.y * cb + x1.y * sb, H, L);
        qH[wb + 64 + j] = H; qL[wb + 64 + j] = L;
    }
    {
        const float* base = k + (size_t)s * DHD;
        float2 x1 = *(const float2*)&base[2 * j];
        float2 x2 = *(const float2*)&base[128 + 2 * j];
        const size_t wb = (size_t)s * DKW;
        uint32_t H, L;
        packpair(x1.x * ca - x2.x * sa, x1.y * cb - x2.y * sb, H, L);
        kH[wb + j] = H;      kL[wb + j] = L;
        packpair(x2.x * ca + x1.x * sa, x2.y * cb + x1.y * sb, H, L);
        kH[wb + 64 + j] = H; kL[wb + 64 + j] = L;
    }
}

// ---------------------------------------------------------------------------
// GEMM on pre-split inputs. 256 threads (8 warps, 64x32 warp tile), 2 CTAs/SM
// so one CTA's barriers overlap the other's mma work. cp.async double-buffer.
// aL fragments loaded AFTER the hi*hi / hi*lo terms to lower register peak.
// ---------------------------------------------------------------------------
#define GP 20
#define OAL_B 10240
#define OBH_B 20480
#define OBL_B 30720
#define BUFW  10240
#define GEMM_SMEM (2 * BUFW * 4)   // 81920 B -> 2 CTAs = 160 KB/SM

__global__ __launch_bounds__(256, 2)
void gemm_presplit(const uint32_t* __restrict__ AH, const uint32_t* __restrict__ AL,
                   const uint32_t* __restrict__ BH, const uint32_t* __restrict__ BL,
                   float* __restrict__ C, int M, int N, int Kw)
{
    extern __shared__ uint32_t smu[];
    const uint32_t sb = smem_u32(smu);

    const int tid  = threadIdx.x;
    const int wid  = tid >> 5, lane = tid & 31;
    const int g    = lane >> 2, tig = lane & 3;
    const int l8   = lane & 7, lb3 = (lane >> 3) & 1, lb4 = (lane >> 4) & 1;
    const int wm   = (wid & 1) * 64;
    const int wn   = (wid >> 1) * 32;
    const int m0   = blockIdx.y * 128, n0 = blockIdx.x * 128;

    const int lr = tid >> 1;
    const int wc = (tid & 1) * 8;
    const uint32_t* gah = AH + (size_t)(m0 + lr) * Kw + wc;
    const uint32_t* gal = AL + (size_t)(m0 + lr) * Kw + wc;
    const uint32_t* gbh = BH + (size_t)(n0 + lr) * Kw + wc;
    const uint32_t* gbl = BL + (size_t)(n0 + lr) * Kw + wc;

#define GISSUE(ci, bufbyte) do {                                            \
        const uint32_t _b = sb + (bufbyte) + (lr * GP + wc) * 4;            \
        const uint32_t* _g;                                                 \
        _g = gah + (ci) * 16; CP16(_b,         _g); CP16(_b + 16,         _g + 4); \
        _g = gal + (ci) * 16; CP16(_b + OAL_B, _g); CP16(_b + OAL_B + 16, _g + 4); \
        _g = gbh + (ci) * 16; CP16(_b + OBH_B, _g); CP16(_b + OBH_B + 16, _g + 4); \
        _g = gbl + (ci) * 16; CP16(_b + OBL_B, _g); CP16(_b + OBL_B + 16, _g + 4); \
    } while (0)

    float c[16][4];
    #pragma unroll
    for (int i = 0; i < 16; ++i)
        #pragma unroll
        for (int j = 0; j < 4; ++j) c[i][j] = 0.f;

    const int nch = Kw / 16;
    GISSUE(0, 0);
    CPCOMMIT();

    for (int c0 = 0; c0 < nch; ++c0) {
        const uint32_t cb = (uint32_t)(c0 & 1) * (BUFW * 4);
        if (c0 + 1 < nch) {
            GISSUE(c0 + 1, (uint32_t)((c0 + 1) & 1) * (BUFW * 4));
            CPCOMMIT();
            CPWAIT1();
        } else {
            CPWAIT0();
        }
        __syncthreads();

        #pragma unroll
        for (int ks = 0; ks < 2; ++ks) {
            const int wb = ks * 8;
            uint32_t aH[4][4], bH[2][4], bL[2][4];
            #pragma unroll
            for (int mt = 0; mt < 4; ++mt) {
                const uint32_t ro = (uint32_t)((wm + mt * 16 + l8 + lb3 * 8) * GP
                                               + wb + lb4 * 4) * 4;
                ldsm_x4(aH[mt], sb + cb + ro);
            }
            #pragma unroll
            for (int p = 0; p < 2; ++p) {
                const uint32_t ro = (uint32_t)((wn + p * 16 + lb4 * 8 + l8) * GP
                                               + wb + lb3 * 4) * 4;
                ldsm_x4(bH[p], sb + cb + OBH_B + ro);
                ldsm_x4(bL[p], sb + cb + OBL_B + ro);
            }
            // term 1: hi*hi
            #pragma unroll
            for (int mt = 0; mt < 4; ++mt)
                #pragma unroll
                for (int nt = 0; nt < 4; ++nt)
                    MMA_BF16(c[mt * 4 + nt], aH[mt], &bH[nt >> 1][(nt & 1) * 2]);
            // term 2: hi*lo
            #pragma unroll
            for (int mt = 0; mt < 4; ++mt)
                #pragma unroll
                for (int nt = 0; nt < 4; ++nt)
                    MMA_BF16(c[mt * 4 + nt], aH[mt], &bL[nt >> 1][(nt & 1) * 2]);
            // term 3: lo*hi  (load aL now, reuse aH registers' slot pressure)
            uint32_t aL[4][4];
            #pragma unroll
            for (int mt = 0; mt < 4; ++mt) {
                const uint32_t ro = (uint32_t)((wm + mt * 16 + l8 + lb3 * 8) * GP
                                               + wb + lb4 * 4) * 4;
                ldsm_x4(aL[mt], sb + cb + OAL_B + ro);
            }
            #pragma unroll
            for (int mt = 0; mt < 4; ++mt)
                #pragma unroll
                for (int nt = 0; nt < 4; ++nt)
                    MMA_BF16(c[mt * 4 + nt], aL[mt], &bH[nt >> 1][(nt & 1) * 2]);
        }
        __syncthreads();
    }
#undef GISSUE

    #pragma unroll
    for (int mt = 0; mt < 4; ++mt)
        #pragma unroll
        for (int nt = 0; nt < 4; ++nt) {
            const float* cc = c[mt * 4 + nt];
            const int row = m0 + wm + mt * 16 + g;
            const int col = n0 + wn + nt * 8 + 2 * tig;
            *(float2*)&C[(size_t)row * N + col]       = make_float2(cc[0], cc[1]);
            *(float2*)&C[(size_t)(row + 8) * N + col] = make_float2(cc[2], cc[3]);
        }
}

// ---------------------------------------------------------------------------
// Flash attention, 512 threads; single-buffer cp.async with skewed overlap:
// K(jt+1) loads during softmax+PV, VT(jt+1) loads during next QK^T.
// ---------------------------------------------------------------------------
#define QP 132
#define VP 36
#define PP 68
#define OFF_QH 0
#define OFF_QL (OFF_QH + 64 * QP)
#define OFF_KH (OFF_QL + 64 * QP)
#define OFF_KL (OFF_KH + 64 * QP)
#define OFF_VTH (OFF_KL + 64 * QP)
#define OFF_VTL (OFF_VTH + 256 * VP)
#define OFF_PS  (OFF_VTL + 256 * VP)
#define OFF_M   (OFF_PS + 64 * PP)
#define OFF_L   (OFF_M + 64)
#define OFF_C   (OFF_L + 64)
#define FA3_SMEM ((OFF_C + 64) * 4)

__global__ __launch_bounds__(512, 1) void flash_mma_bf16(
    const uint32_t* __restrict__ Qh, const uint32_t* __restrict__ Ql,
    const uint32_t* __restrict__ Kh, const uint32_t* __restrict__ Kl,
    const uint32_t* __restrict__ VtH, const uint32_t* __restrict__ VtL,
    uint32_t* __restrict__ AHo, uint32_t* __restrict__ ALo)
{
    extern __shared__ uint32_t smu[];
    float* smf = (float*)smu;
    const uint32_t sb = smem_u32(smu);

    const int tid  = threadIdx.x;
    const int wid  = tid >> 5, lane = tid & 31;
    const int g    = lane >> 2, tig = lane & 3;
    const int l8   = lane & 7, lb3 = (lane >> 3) & 1, lb4 = (lane >> 4) & 1;
    const int h    = blockIdx.y;
    const int it   = gridDim.x - 1 - blockIdx.x;

    const int wqm = (wid & 1) * 32;
    const int wqn = (wid >> 1) * 8;
    const int wpm = (wid & 3) * 16;
    const int wpn = (wid >> 2) * 64;

    const int lr = tid & 63, lq = (tid >> 6) * 16;
    const int vd = tid >> 1, vh = (tid & 1) * 16;
    const int srow = tid >> 3, sseg = (tid & 7) * 8;

#define ISSUE_K(jt_) do {                                                   \
        const uint32_t* _sH = Kh + (size_t)((jt_) * 64 + lr) * DKW + lq;    \
        const uint32_t* _sL = Kl + (size_t)((jt_) * 64 + lr) * DKW + lq;    \
        const uint32_t _dh = sb + (uint32_t)(OFF_KH + lr * QP + lq) * 4;    \
        const uint32_t _dl = sb + (uint32_t)(OFF_KL + lr * QP + lq) * 4;    \
        CP16(_dh, _sH); CP16(_dh + 16, _sH + 4);                            \
        CP16(_dh + 32, _sH + 8); CP16(_dh + 48, _sH + 12);                  \
        CP16(_dl, _sL); CP16(_dl + 16, _sL + 4);                            \
        CP16(_dl + 32, _sL + 8); CP16(_dl + 48, _sL + 12);                  \
    } while (0)

#define ISSUE_VT(jt_) do {                                                  \
        const uint32_t* _sH = VtH + (size_t)vd * SW + (jt_) * 32 + vh;      \
        const uint32_t* _sL = VtL + (size_t)vd * SW + (jt_) * 32 + vh;      \
        const uint32_t _dh = sb + (uint32_t)(OFF_VTH + vd * VP + vh) * 4;   \
        const uint32_t _dl = sb + (uint32_t)(OFF_VTL + vd * VP + vh) * 4;   \
        CP16(_dh, _sH); CP16(_dh + 16, _sH + 4);                            \
        CP16(_dh + 32, _sH + 8); CP16(_dh + 48, _sH + 12);                  \
        CP16(_dl, _sL); CP16(_dl + 16, _sL + 4);                            \
        CP16(_dl + 32, _sL + 8); CP16(_dl + 48, _sL + 12);                  \
    } while (0)

    // prologue loads for tile 0
    ISSUE_K(0);  CPCOMMIT();
    ISSUE_VT(0); CPCOMMIT();

    // ---- stage Q + init state (overlaps with prologue cp.async) ----
    {
        const uint32_t* sH = Qh + (size_t)(it * 64 + lr) * KW + h * DKW + lq;
        const uint32_t* sL = Ql + (size_t)(it * 64 + lr) * KW + h * DKW + lq;
        const int d = lr * QP + lq;
        #pragma unroll
        for (int i = 0; i < 4; ++i) {
            *(uint4*)&smu[OFF_QH + d + 4 * i] = *(const uint4*)(sH + 4 * i);
            *(uint4*)&smu[OFF_QL + d + 4 * i] = *(const uint4*)(sL + 4 * i);
        }
        if (tid < 64) { smf[OFF_M + tid] = -1e30f; smf[OFF_L + tid] = 0.f; }
    }

    float o[8][4];
    #pragma unroll
    for (int i = 0; i < 8; ++i)
        #pragma unroll
        for (int j = 0; j < 4; ++j) o[i][j] = 0.f;

    const int rowq0 = wqm + l8 + lb3 * 8;
    const int rowp  = wpm + l8 + lb3 * 8;
    const uint32_t kfrag_base = (lb4 ? OFF_KL : OFF_KH) * 4;
    const int rowk  = wqn + l8;

    for (int jt = 0; jt <= it; ++jt) {
        CPWAIT1();          // K(jt) landed (VT(jt) may still be in flight)
        __syncthreads();    // K visible to all; prev-iter PS readers done

        // ---- Phase A: S = Q K^T ----
        {
            float s[2][4];
            #pragma unroll
            for (int a = 0; a < 2; ++a)
                #pragma unroll
                for (int j = 0; j < 4; ++j) s[a][j] = 0.f;

            #pragma unroll 4
            for (int ks = 0; ks < 16; ++ks) {
                const int wb = ks * 8;
                uint32_t aH0[4], aH1[4], aL0[4], aL1[4], bHL[4];
                const uint32_t qo = (uint32_t)(rowq0 * QP + wb + lb4 * 4) * 4;
                ldsm_x4(aH0, sb + OFF_QH * 4 + qo);
                ldsm_x4(aH1, sb + OFF_QH * 4 + qo + 16 * QP * 4);
                ldsm_x4(aL0, sb + OFF_QL * 4 + qo);
                ldsm_x4(aL1, sb + OFF_QL * 4 + qo + 16 * QP * 4);
                ldsm_x4(bHL, sb + kfrag_base
                              + (uint32_t)(rowk * QP + wb + lb3 * 4) * 4);
                MMA_BF16(s[0], aH0, &bHL[0]); MMA_BF16(s[1], aH1, &bHL[0]);
                MMA_BF16(s[0], aH0, &bHL[2]); MMA_BF16(s[1], aH1, &bHL[2]);
                MMA_BF16(s[0], aL0, &bHL[0]); MMA_BF16(s[1], aL1, &bHL[0]);
            }
            #pragma unroll
            for (int mf = 0; mf < 2; ++mf) {
                const int row = wqm + mf * 16 + g;
                const int col = wqn + 2 * tig;
                *(float2*)&smf[OFF_PS + row * PP + col]       = make_float2(s[mf][0], s[mf][1]);
                *(float2*)&smf[OFF_PS + (row + 8) * PP + col] = make_float2(s[mf][2], s[mf][3]);
            }
        }
        __syncthreads();    // A done: PS complete, K buffer free

        if (jt < it) { ISSUE_K(jt + 1); CPCOMMIT(); }   // overlaps B + C

        // ---- Phase B: online softmax; pack P in place ----
        {
            const bool diag = (jt == it);
            float pv[8];
            float mx = -1e30f;
            #pragma unroll
            for (int c = 0; c < 8; ++c) {
                const int col = sseg + c;
                float val = smf[OFF_PS + srow * PP + col] * 0.0625f;
                if (diag && col > srow) val = -1e30f;
                pv[c] = val;
                mx = fmaxf(mx, val);
            }
            mx = fmaxf(mx, __shfl_xor_sync(0xffffffffu, mx, 1));
            mx = fmaxf(mx, __shfl_xor_sync(0xffffffffu, mx, 2));
            mx = fmaxf(mx, __shfl_xor_sync(0xffffffffu, mx, 4));
            const float m_old = smf[OFF_M + srow];
            const float m_new = fmaxf(m_old, mx);
            const float corr  = __expf(m_old - m_new);
            float lsum = 0.f;
            #pragma unroll
            for (int c = 0; c < 8; ++c) {
                pv[c] = __expf(pv[c] - m_new);
                lsum += pv[c];
            }
            lsum += __shfl_xor_sync(0xffffffffu, lsum, 1);
            lsum += __shfl_xor_sync(0xffffffffu, lsum, 2);
            lsum += __shfl_xor_sync(0xffffffffu, lsum, 4);
            if ((tid & 7) == 0) {
                smf[OFF_M + srow] = m_new;
                smf[OFF_L + srow] = smf[OFF_L + srow] * corr + lsum;
                smf[OFF_C + srow] = corr;
            }
            __syncwarp();
            const int wbse = OFF_PS + srow * PP + (tid & 7) * 4;
            #pragma unroll
            for (int i = 0; i < 4; ++i) {
                uint32_t H, L;
                packpair(pv[2 * i], pv[2 * i + 1], H, L);
                smu[wbse + i]      = H;
                smu[wbse + 32 + i] = L;
            }
        }
        if (jt < it) CPWAIT1(); else CPWAIT0();   // VT(jt) landed
        __syncthreads();                          // B->C + VT visibility

        // ---- Phase C: acc = acc*corr + P @ V ----
        {
            const float c_lo = smf[OFF_C + wpm + g];
            const float c_hi = smf[OFF_C + wpm + g + 8];
            #pragma unroll
            for (int nf = 0; nf < 8; ++nf) {
                o[nf][0] *= c_lo; o[nf][1] *= c_lo;
                o[nf][2] *= c_hi; o[nf][3] *= c_hi;
            }
            #pragma unroll
            for (int ks = 0; ks < 4; ++ks) {
                const int wb = ks * 8;
                uint32_t pH[4], pL[4], vH[4][4], vL[4][4];
                const uint32_t po = (uint32_t)(rowp * PP + wb + lb4 * 4) * 4;
                ldsm_x4(pH, sb + OFF_PS * 4 + po);
                ldsm_x4(pL, sb + OFF_PS * 4 + po + 128);
                #pragma unroll
                for (int vg = 0; vg < 4; ++vg) {
                    const uint32_t vo = (uint32_t)(
                        (wpn + vg * 16 + lb4 * 8 + l8) * VP + wb + lb3 * 4) * 4;
                    ldsm_x4(vH[vg], sb + OFF_VTH * 4 + vo);
                    ldsm_x4(vL[vg], sb + OFF_VTL * 4 + vo);
                }
                #pragma unroll
                for (int vg = 0; vg < 4; ++vg) {
                    MMA_BF16(o[vg * 2],     pH, &vH[vg][0]);
                    MMA_BF16(o[vg * 2 + 1], pH, &vH[vg][2]);
                }
                #pragma unroll
                for (int vg = 0; vg < 4; ++vg) {
                    MMA_BF16(o[vg * 2],     pH, &vL[vg][0]);
                    MMA_BF16(o[vg * 2 + 1], pH, &vL[vg][2]);
                }
                #pragma unroll
                for (int vg = 0; vg < 4; ++vg) {
                    MMA_BF16(o[vg * 2],     pL, &vH[vg][0]);
                    MMA_BF16(o[vg * 2 + 1], pL, &vH[vg][2]);
                }
            }
        }
        __syncthreads();    // C done: VT buffer free
        if (jt < it) { ISSUE_VT(jt + 1); CPCOMMIT(); }  // overlaps next A
    }
#undef ISSUE_K
#undef ISSUE_VT

    // ---- normalize and write packed attn ----
    {
        const float inv_lo = 1.0f / smf[OFF_L + wpm + g];
        const float inv_hi = 1.0f / smf[OFF_L + wpm + g + 8];
        const size_t row_lo = (size_t)(it * 64 + wpm + g);
        const size_t row_hi = row_lo + 8;
        #pragma unroll
        for (int nf = 0; nf < 8; ++nf) {
            const int wcol = h * DKW + (wpn >> 1) + nf * 4 + tig;
            uint32_t H, L;
            packpair(o[nf][0] * inv_lo, o[nf][1] * inv_lo, H, L);
            AHo[row_lo * KW + wcol] = H;
            ALo[row_lo * KW + wcol] = L;
            packpair(o[nf][2] * inv_hi, o[nf][3] * inv_hi, H, L);
            AHo[row_hi * KW + wcol] = H;
            ALo[row_hi * KW + wcol] = L;
        }
    }
}

// ---------------------------------------------------------------------------
extern "C" void kernel_launch(void* const* d_in, const int* in_sizes, int n_in,
                              void* d_out, int out_size)
{
    const float* X   = (const float*)d_in[0];
    const int*   pos = (const int*)  d_in[1];
    const float* wq  = (const float*)d_in[2];
    const float* wk  = (const float*)d_in[3];
    const float* wv  = (const float*)d_in[4];
    const float* wo  = (const float*)d_in[5];
    float* out = (float*)d_out;

    float *q, *k, *v;
    uint32_t *xH, *xL, *qH, *qL, *kH, *kL, *vtH, *vtL, *aH, *aL;
    uint32_t *wqH, *wqL, *wkH, *wkL, *wvH, *wvL, *woH, *woL;
    cudaGetSymbolAddress((void**)&q,   g_q);
    cudaGetSymbolAddress((void**)&k,   g_k);
    cudaGetSymbolAddress((void**)&v,   g_v);
    cudaGetSymbolAddress((void**)&xH,  g_xH);  cudaGetSymbolAddress((void**)&xL,  g_xL);
    cudaGetSymbolAddress((void**)&qH,  g_qH);  cudaGetSymbolAddress((void**)&qL,  g_qL);
    cudaGetSymbolAddress((void**)&kH,  g_kH);  cudaGetSymbolAddress((void**)&kL,  g_kL);
    cudaGetSymbolAddress((void**)&vtH, g_vtH); cudaGetSymbolAddress((void**)&vtL, g_vtL);
    cudaGetSymbolAddress((void**)&aH,  g_aH);  cudaGetSymbolAddress((void**)&aL,  g_aL);
    cudaGetSymbolAddress((void**)&wqH, g_wqH); cudaGetSymbolAddress((void**)&wqL, g_wqL);
    cudaGetSymbolAddress((void**)&wkH, g_wkH); cudaGetSymbolAddress((void**)&wkL, g_wkL);
    cudaGetSymbolAddress((void**)&wvH, g_wvH); cudaGetSymbolAddress((void**)&wvL, g_wvL);
    cudaGetSymbolAddress((void**)&woH, g_woH); cudaGetSymbolAddress((void**)&woL, g_woL);

    cudaFuncSetAttribute(gemm_presplit,
                         cudaFuncAttributeMaxDynamicSharedMemorySize, GEMM_SMEM);
    cudaFuncSetAttribute(flash_mma_bf16,
                         cudaFuncAttributeMaxDynamicSharedMemorySize, FA3_SMEM);

    dim3 tb(32, 8);
    transpose_split<<<dim3(HID / 32, HID / 32), tb>>>(wq, wqH, wqL, HID, HID);   // 1
    transpose_split<<<dim3(DHD / 32, HID / 32), tb>>>(wk, wkH, wkL, HID, DHD);   // 2
    split_rows<<<S_LEN * KW / (256 * 4), 256>>>(X, xH, xL);                      // 3
    gemm_presplit<<<dim3(HID / 128, S_LEN / 128), 256, GEMM_SMEM>>>(             // 4
        xH, xL, wqH, wqL, q, S_LEN, HID, KW);
    transpose_split<<<dim3(DHD / 32, HID / 32), tb>>>(wv, wvH, wvL, HID, DHD);   // 5
    gemm_presplit<<<dim3(DHD / 128, S_LEN / 128), 256, GEMM_SMEM>>>(             // 6
        xH, xL, wkH, wkL, k, S_LEN, DHD, KW);
    gemm_presplit<<<dim3(DHD / 128, S_LEN / 128), 256, GEMM_SMEM>>>(             // 7
        xH, xL, wvH, wvL, v, S_LEN, DHD, KW);
    rope_split<<<S_LEN, 64>>>(q, k, pos, qH, qL, kH, kL);                        // 8
    transpose_split<<<dim3(HID / 32, HID / 32), tb>>>(wo, woH, woL, HID, HID);   // 9
    transpose_split<<<dim3(DHD / 32, S_LEN / 32), tb>>>(v, vtH, vtL, S_LEN, DHD);// 10
    flash_mma_bf16<<<dim3(S_LEN / 64, NH), 512, FA3_SMEM>>>(                     // 11
        qH, qL, kH, kL, vtH, vtL, aH, aL);
    gemm_presplit<<<dim3(HID / 128, S_LEN / 128), 256, GEMM_SMEM>>>(             // 12
        aH, aL, woH, woL, out, S_LEN, HID, KW);
}

// round 15
// speedup vs baseline: 1.1149x; 1.0820x over previous
#include <cuda_runtime.h>
#include <cuda_bf16.h>
#include <cstdint>

#define S_LEN 4096
#define HID   2048
#define NH    8
#define DHD   256
#define KW    1024      // HID/2 words per row (packed bf16x2)
#define DKW   128       // DHD/2 words
#define SW    2048      // S_LEN/2 words

// ---------------------------------------------------------------------------
// Scratch (static device globals: allocation-free per harness rules)
// ---------------------------------------------------------------------------
__device__ float    g_q[S_LEN * HID];
__device__ float    g_kv[S_LEN * 512];                     // fused K|V fp32
__device__ uint32_t g_xH[S_LEN * KW],  g_xL[S_LEN * KW];
__device__ uint32_t g_qH[S_LEN * KW],  g_qL[S_LEN * KW];
__device__ uint32_t g_kH[S_LEN * DKW], g_kL[S_LEN * DKW];
__device__ uint32_t g_vtH[DHD * SW],   g_vtL[DHD * SW];
__device__ uint32_t g_aH[S_LEN * KW],  g_aL[S_LEN * KW];
__device__ uint32_t g_wqH[HID * KW],   g_wqL[HID * KW];
__device__ uint32_t g_wkvH[512 * KW],  g_wkvL[512 * KW];   // concat wk|wv (K-major)
__device__ uint32_t g_woH[HID * KW],   g_woL[HID * KW];

// ---------------------------------------------------------------------------
// helpers
// ---------------------------------------------------------------------------
__device__ __forceinline__ uint32_t smem_u32(const void* p) {
    uint32_t a;
    asm("{ .reg .u64 t; cvta.to.shared.u64 t, %1; cvt.u32.u64 %0, t; }"
        : "=r"(a) : "l"(p));
    return a;
}
__device__ __forceinline__ float bf16_rn_f32(float x) {
    return __bfloat162float(__float2bfloat16(x));
}
__device__ __forceinline__ uint32_t bf16pack(float lo_k, float hi_k) {
    uint32_t r;
    asm("cvt.rn.bf16x2.f32 %0, %1, %2;" : "=r"(r) : "f"(hi_k), "f"(lo_k));
    return r;
}
__device__ __forceinline__ void packpair(float a, float b, uint32_t& H, uint32_t& L) {
    H = bf16pack(a, b);
    L = bf16pack(a - bf16_rn_f32(a), b - bf16_rn_f32(b));
}
__device__ __forceinline__ void split_pack4(float4 v, uint32_t* h, uint32_t* l) {
    packpair(v.x, v.y, h[0], l[0]);
    packpair(v.z, v.w, h[1], l[1]);
}
__device__ __forceinline__ void ldsm_x4(uint32_t* r, uint32_t addr) {
    asm volatile("ldmatrix.sync.aligned.m8n8.x4.shared.b16 {%0,%1,%2,%3}, [%4];"
        : "=r"(r[0]), "=r"(r[1]), "=r"(r[2]), "=r"(r[3]) : "r"(addr));
}
#define MMA_BF16(c, a, b)                                                   \
    asm volatile("mma.sync.aligned.m16n8k16.row.col.f32.bf16.bf16.f32 "     \
        "{%0,%1,%2,%3}, {%4,%5,%6,%7}, {%8,%9}, {%0,%1,%2,%3};"             \
        : "+f"((c)[0]), "+f"((c)[1]), "+f"((c)[2]), "+f"((c)[3])            \
        : "r"((a)[0]), "r"((a)[1]), "r"((a)[2]), "r"((a)[3]),               \
          "r"((b)[0]), "r"((b)[1]))
#define CP16(sm, gm) \
    asm volatile("cp.async.cg.shared.global [%0], [%1], 16;" :: "r"(sm), "l"(gm))
#define CPCOMMIT() asm volatile("cp.async.commit_group;")
#define CPWAIT0()  asm volatile("cp.async.wait_group 0;")
#define CPWAIT1()  asm volatile("cp.async.wait_group 1;")

// ---------------------------------------------------------------------------
// split_rows: fp32 [rows][2*Kw] -> packed hi/lo u32 [rows][Kw]
// ---------------------------------------------------------------------------
__global__ void split_rows(const float* __restrict__ in,
                           uint32_t* __restrict__ oH, uint32_t* __restrict__ oL)
{
    const size_t t = (size_t)blockIdx.x * blockDim.x + threadIdx.x;
    const float* p = in + t * 8;
    uint32_t h[2], l[2], h2[2], l2[2];
    split_pack4(*(const float4*)p, h, l);
    split_pack4(*(const float4*)(p + 4), h2, l2);
    *(uint4*)&oH[t * 4] = make_uint4(h[0], h[1], h2[0], h2[1]);
    *(uint4*)&oL[t * 4] = make_uint4(l[0], l[1], l2[0], l2[1]);
}

// ---------------------------------------------------------------------------
// transpose_split: in [R rows][C cols] (row stride ldin, col offset incoff)
//   -> out hi/lo u32 [(outoff + c)][R/2] (pairs along R)
// ---------------------------------------------------------------------------
__global__ void transpose_split(const float* __restrict__ in,
                                uint32_t* __restrict__ oH, uint32_t* __restrict__ oL,
                                int R, int C, int ldin, int incoff, int outoff)
{
    __shared__ float t[32][33];
    const int c0 = blockIdx.x * 32, r0 = blockIdx.y * 32;
    const int tx = threadIdx.x, ty = threadIdx.y;
    #pragma unroll
    for (int j = 0; j < 4; ++j)
        t[ty + 8 * j][tx] = in[(size_t)(r0 + ty + 8 * j) * ldin + incoff + c0 + tx];
    __syncthreads();
    const int Rw = R >> 1;
    #pragma unroll
    for (int j = 0; j < 2; ++j) {
        const int jj = ty + 8 * j;
        const float a = t[2 * jj][tx], b = t[2 * jj + 1][tx];
        uint32_t H, L;
        packpair(a, b, H, L);
        oH[(size_t)(outoff + c0 + tx) * Rw + (r0 >> 1) + jj] = H;
        oL[(size_t)(outoff + c0 + tx) * Rw + (r0 >> 1) + jj] = L;
    }
}

// ---------------------------------------------------------------------------
// rope_split: q from g_q (stride HID); k from fused kv (stride 512, cols 0-255)
// ---------------------------------------------------------------------------
__global__ void rope_split(const float* __restrict__ q, const float* __restrict__ kv,
                           const int* __restrict__ pos,
                           uint32_t* __restrict__ qH, uint32_t* __restrict__ qL,
                           uint32_t* __restrict__ kH, uint32_t* __restrict__ kL)
{
    const int s = blockIdx.x;
    const int j = threadIdx.x;
    const float p = (float)pos[s];
    const float ia = 1.0f / powf(10000.0f, (float)(2 * j)     * (1.0f / 128.0f));
    const float ib = 1.0f / powf(10000.0f, (float)(2 * j + 1) * (1.0f / 128.0f));
    float sa, ca, sb, cb;
    sincosf(p * ia, &sa, &ca);
    sincosf(p * ib, &sb, &cb);

    #pragma unroll
    for (int h = 0; h < NH; ++h) {
        const float* base = q + (size_t)s * HID + h * DHD;
        float2 x1 = *(const float2*)&base[2 * j];
        float2 x2 = *(const float2*)&base[128 + 2 * j];
        const size_t wb = (size_t)s * KW + h * DKW;
        uint32_t H, L;
        packpair(x1.x * ca - x2.x * sa, x1.y * cb - x2.y * sb, H, L);
        qH[wb + j] = H;      qL[wb + j] = L;
        packpair(x2.x * ca + x1.x * sa, x2.y * cb + x1.y * sb, H, L);
        qH[wb + 64 + j] = H; qL[wb + 64 + j] = L;
    }
    {
        const float* base = kv + (size_t)s * 512;
        float2 x1 = *(const float2*)&base[2 * j];
        float2 x2 = *(const float2*)&base[128 + 2 * j];
        const size_t wb = (size_t)s * DKW;
        uint32_t H, L;
        packpair(x1.x * ca - x2.x * sa, x1.y * cb - x2.y * sb, H, L);
        kH[wb + j] = H;      kL[wb + j] = L;
        packpair(x2.x * ca + x1.x * sa, x2.y * cb + x1.y * sb, H, L);
        kH[wb + 64 + j] = H; kL[wb + 64 + j] = L;
    }
}

// ---------------------------------------------------------------------------
// GEMM on pre-split inputs (unchanged from R14: 256 thr, 2 CTAs/SM, cp.async).
// ---------------------------------------------------------------------------
#define GP 20
#define OAL_B 10240
#define OBH_B 20480
#define OBL_B 30720
#define BUFW  10240
#define GEMM_SMEM (2 * BUFW * 4)

__global__ __launch_bounds__(256, 2)
void gemm_presplit(const uint32_t* __restrict__ AH, const uint32_t* __restrict__ AL,
                   const uint32_t* __restrict__ BH, const uint32_t* __restrict__ BL,
                   float* __restrict__ C, int M, int N, int Kw)
{
    extern __shared__ uint32_t smu[];
    const uint32_t sb = smem_u32(smu);

    const int tid  = threadIdx.x;
    const int wid  = tid >> 5, lane = tid & 31;
    const int g    = lane >> 2, tig = lane & 3;
    const int l8   = lane & 7, lb3 = (lane >> 3) & 1, lb4 = (lane >> 4) & 1;
    const int wm   = (wid & 1) * 64;
    const int wn   = (wid >> 1) * 32;
    const int m0   = blockIdx.y * 128, n0 = blockIdx.x * 128;

    const int lr = tid >> 1;
    const int wc = (tid & 1) * 8;
    const uint32_t* gah = AH + (size_t)(m0 + lr) * Kw + wc;
    const uint32_t* gal = AL + (size_t)(m0 + lr) * Kw + wc;
    const uint32_t* gbh = BH + (size_t)(n0 + lr) * Kw + wc;
    const uint32_t* gbl = BL + (size_t)(n0 + lr) * Kw + wc;

#define GISSUE(ci, bufbyte) do {                                            \
        const uint32_t _b = sb + (bufbyte) + (lr * GP + wc) * 4;            \
        const uint32_t* _g;                                                 \
        _g = gah + (ci) * 16; CP16(_b,         _g); CP16(_b + 16,         _g + 4); \
        _g = gal + (ci) * 16; CP16(_b + OAL_B, _g); CP16(_b + OAL_B + 16, _g + 4); \
        _g = gbh + (ci) * 16; CP16(_b + OBH_B, _g); CP16(_b + OBH_B + 16, _g + 4); \
        _g = gbl + (ci) * 16; CP16(_b + OBL_B, _g); CP16(_b + OBL_B + 16, _g + 4); \
    } while (0)

    float c[16][4];
    #pragma unroll
    for (int i = 0; i < 16; ++i)
        #pragma unroll
        for (int j = 0; j < 4; ++j) c[i][j] = 0.f;

    const int nch = Kw / 16;
    GISSUE(0, 0);
    CPCOMMIT();

    for (int c0 = 0; c0 < nch; ++c0) {
        const uint32_t cb = (uint32_t)(c0 & 1) * (BUFW * 4);
        if (c0 + 1 < nch) {
            GISSUE(c0 + 1, (uint32_t)((c0 + 1) & 1) * (BUFW * 4));
            CPCOMMIT();
            CPWAIT1();
        } else {
            CPWAIT0();
        }
        __syncthreads();

        #pragma unroll
        for (int ks = 0; ks < 2; ++ks) {
            const int wb = ks * 8;
            uint32_t aH[4][4], bH[2][4], bL[2][4];
            #pragma unroll
            for (int mt = 0; mt < 4; ++mt) {
                const uint32_t ro = (uint32_t)((wm + mt * 16 + l8 + lb3 * 8) * GP
                                               + wb + lb4 * 4) * 4;
                ldsm_x4(aH[mt], sb + cb + ro);
            }
            #pragma unroll
            for (int p = 0; p < 2; ++p) {
                const uint32_t ro = (uint32_t)((wn + p * 16 + lb4 * 8 + l8) * GP
                                               + wb + lb3 * 4) * 4;
                ldsm_x4(bH[p], sb + cb + OBH_B + ro);
                ldsm_x4(bL[p], sb + cb + OBL_B + ro);
            }
            #pragma unroll
            for (int mt = 0; mt < 4; ++mt)
                #pragma unroll
                for (int nt = 0; nt < 4; ++nt)
                    MMA_BF16(c[mt * 4 + nt], aH[mt], &bH[nt >> 1][(nt & 1) * 2]);
            #pragma unroll
            for (int mt = 0; mt < 4; ++mt)
                #pragma unroll
                for (int nt = 0; nt < 4; ++nt)
                    MMA_BF16(c[mt * 4 + nt], aH[mt], &bL[nt >> 1][(nt & 1) * 2]);
            uint32_t aL[4][4];
            #pragma unroll
            for (int mt = 0; mt < 4; ++mt) {
                const uint32_t ro = (uint32_t)((wm + mt * 16 + l8 + lb3 * 8) * GP
                                               + wb + lb4 * 4) * 4;
                ldsm_x4(aL[mt], sb + cb + OAL_B + ro);
            }
            #pragma unroll
            for (int mt = 0; mt < 4; ++mt)
                #pragma unroll
                for (int nt = 0; nt < 4; ++nt)
                    MMA_BF16(c[mt * 4 + nt], aL[mt], &bH[nt >> 1][(nt & 1) * 2]);
        }
        __syncthreads();
    }
#undef GISSUE

    #pragma unroll
    for (int mt = 0; mt < 4; ++mt)
        #pragma unroll
        for (int nt = 0; nt < 4; ++nt) {
            const float* cc = c[mt * 4 + nt];
            const int row = m0 + wm + mt * 16 + g;
            const int col = n0 + wn + nt * 8 + 2 * tig;
            *(float2*)&C[(size_t)row * N + col]       = make_float2(cc[0], cc[1]);
            *(float2*)&C[(size_t)(row + 8) * N + col] = make_float2(cc[2], cc[3]);
        }
}

// ---------------------------------------------------------------------------
// Flash attention, 512 threads; skewed cp.async (as R14);
// Phase A remapped 4m x 4n (less fragment duplication) + k-step ping-pong;
// Phase C vg-interleaved ldsm/mma.
// ---------------------------------------------------------------------------
#define QP 132
#define VP 36
#define PP 68
#define OFF_QH 0
#define OFF_QL (OFF_QH + 64 * QP)
#define OFF_KH (OFF_QL + 64 * QP)
#define OFF_KL (OFF_KH + 64 * QP)
#define OFF_VTH (OFF_KL + 64 * QP)
#define OFF_VTL (OFF_VTH + 256 * VP)
#define OFF_PS  (OFF_VTL + 256 * VP)
#define OFF_M   (OFF_PS + 64 * PP)
#define OFF_L   (OFF_M + 64)
#define OFF_C   (OFF_L + 64)
#define FA3_SMEM ((OFF_C + 64) * 4)

__global__ __launch_bounds__(512, 1) void flash_mma_bf16(
    const uint32_t* __restrict__ Qh, const uint32_t* __restrict__ Ql,
    const uint32_t* __restrict__ Kh, const uint32_t* __restrict__ Kl,
    const uint32_t* __restrict__ VtH, const uint32_t* __restrict__ VtL,
    uint32_t* __restrict__ AHo, uint32_t* __restrict__ ALo)
{
    extern __shared__ uint32_t smu[];
    float* smf = (float*)smu;
    const uint32_t sb = smem_u32(smu);

    const int tid  = threadIdx.x;
    const int wid  = tid >> 5, lane = tid & 31;
    const int g    = lane >> 2, tig = lane & 3;
    const int l8   = lane & 7, lb3 = (lane >> 3) & 1, lb4 = (lane >> 4) & 1;
    const int h    = blockIdx.y;
    const int it   = gridDim.x - 1 - blockIdx.x;

    // Phase A: 4m x 4n (16-row, 16-col warp tile)
    const int wqm = (wid & 3) * 16;
    const int wqn = (wid >> 2) * 16;
    // Phase C: 4m x 4n over 64x256 (unchanged)
    const int wpm = (wid & 3) * 16;
    const int wpn = (wid >> 2) * 64;

    const int lr = tid & 63, lq = (tid >> 6) * 16;
    const int vd = tid >> 1, vh = (tid & 1) * 16;
    const int srow = tid >> 3, sseg = (tid & 7) * 8;

#define ISSUE_K(jt_) do {                                                   \
        const uint32_t* _sH = Kh + (size_t)((jt_) * 64 + lr) * DKW + lq;    \
        const uint32_t* _sL = Kl + (size_t)((jt_) * 64 + lr) * DKW + lq;    \
        const uint32_t _dh = sb + (uint32_t)(OFF_KH + lr * QP + lq) * 4;    \
        const uint32_t _dl = sb + (uint32_t)(OFF_KL + lr * QP + lq) * 4;    \
        CP16(_dh, _sH); CP16(_dh + 16, _sH + 4);                            \
        CP16(_dh + 32, _sH + 8); CP16(_dh + 48, _sH + 12);                  \
        CP16(_dl, _sL); CP16(_dl + 16, _sL + 4);                            \
        CP16(_dl + 32, _sL + 8); CP16(_dl + 48, _sL + 12);                  \
    } while (0)

#define ISSUE_VT(jt_) do {                                                  \
        const uint32_t* _sH = VtH + (size_t)vd * SW + (jt_) * 32 + vh;      \
        const uint32_t* _sL = VtL + (size_t)vd * SW + (jt_) * 32 + vh;      \
        const uint32_t _dh = sb + (uint32_t)(OFF_VTH + vd * VP + vh) * 4;   \
        const uint32_t _dl = sb + (uint32_t)(OFF_VTL + vd * VP + vh) * 4;   \
        CP16(_dh, _sH); CP16(_dh + 16, _sH + 4);                            \
        CP16(_dh + 32, _sH + 8); CP16(_dh + 48, _sH + 12);                  \
        CP16(_dl, _sL); CP16(_dl + 16, _sL + 4);                            \
        CP16(_dl + 32, _sL + 8); CP16(_dl + 48, _sL + 12);                  \
    } while (0)

    ISSUE_K(0);  CPCOMMIT();
    ISSUE_VT(0); CPCOMMIT();

    // ---- stage Q + init state (overlaps prologue cp.async) ----
    {
        const uint32_t* sH = Qh + (size_t)(it * 64 + lr) * KW + h * DKW + lq;
        const uint32_t* sL = Ql + (size_t)(it * 64 + lr) * KW + h * DKW + lq;
        const int d = lr * QP + lq;
        #pragma unroll
        for (int i = 0; i < 4; ++i) {
            *(uint4*)&smu[OFF_QH + d + 4 * i] = *(const uint4*)(sH + 4 * i);
            *(uint4*)&smu[OFF_QL + d + 4 * i] = *(const uint4*)(sL + 4 * i);
        }
        if (tid < 64) { smf[OFF_M + tid] = -1e30f; smf[OFF_L + tid] = 0.f; }
    }

    float o[8][4];
    #pragma unroll
    for (int i = 0; i < 8; ++i)
        #pragma unroll
        for (int j = 0; j < 4; ++j) o[i][j] = 0.f;

    const int rowq  = wqm + l8 + lb3 * 8;
    const int rowk0 = wqn + l8;
    const int rowk1 = wqn + 8 + l8;
    const int rowp  = wpm + l8 + lb3 * 8;
    const uint32_t kfrag_base = (lb4 ? OFF_KL : OFF_KH) * 4;

    for (int jt = 0; jt <= it; ++jt) {
        CPWAIT1();          // K(jt) landed (VT(jt) may still be in flight)
        __syncthreads();

        // ---- Phase A: S = Q K^T  (16 k-steps, ping-pong prefetch) ----
        {
            float s[2][4];
            #pragma unroll
            for (int a = 0; a < 2; ++a)
                #pragma unroll
                for (int j = 0; j < 4; ++j) s[a][j] = 0.f;

            uint32_t fH[2][4], fL[2][4], b0[2][4], b1[2][4];
#define LDFRAG(ks_, bf_) do {                                               \
        const int _wb = (ks_) * 8;                                          \
        const uint32_t _qo = (uint32_t)(rowq * QP + _wb + lb4 * 4) * 4;     \
        ldsm_x4(fH[bf_], sb + OFF_QH * 4 + _qo);                            \
        ldsm_x4(fL[bf_], sb + OFF_QL * 4 + _qo);                            \
        ldsm_x4(b0[bf_], sb + kfrag_base                                    \
                          + (uint32_t)(rowk0 * QP + _wb + lb3 * 4) * 4);    \
        ldsm_x4(b1[bf_], sb + kfrag_base                                    \
                          + (uint32_t)(rowk1 * QP + _wb + lb3 * 4) * 4);    \
    } while (0)
            LDFRAG(0, 0);
            #pragma unroll
            for (int ks = 0; ks < 16; ++ks) {
                const int bf = ks & 1;
                if (ks < 15) LDFRAG(ks + 1, bf ^ 1);
                MMA_BF16(s[0], fH[bf], &b0[bf][0]);   // hi*hi
                MMA_BF16(s[1], fH[bf], &b1[bf][0]);
                MMA_BF16(s[0], fH[bf], &b0[bf][2]);   // hi*lo
                MMA_BF16(s[1], fH[bf], &b1[bf][2]);
                MMA_BF16(s[0], fL[bf], &b0[bf][0]);   // lo*hi
                MMA_BF16(s[1], fL[bf], &b1[bf][0]);
            }
#undef LDFRAG
            #pragma unroll
            for (int nf = 0; nf < 2; ++nf) {
                const int row = wqm + g;
                const int col = wqn + nf * 8 + 2 * tig;
                *(float2*)&smf[OFF_PS + row * PP + col]       = make_float2(s[nf][0], s[nf][1]);
                *(float2*)&smf[OFF_PS + (row + 8) * PP + col] = make_float2(s[nf][2], s[nf][3]);
            }
        }
        __syncthreads();    // A done: PS complete, K buffer free

        if (jt < it) { ISSUE_K(jt + 1); CPCOMMIT(); }

        // ---- Phase B: online softmax; pack P in place ----
        {
            const bool diag = (jt == it);
            float pv[8];
            float mx = -1e30f;
            #pragma unroll
            for (int c = 0; c < 8; ++c) {
                const int col = sseg + c;
                float val = smf[OFF_PS + srow * PP + col] * 0.0625f;
                if (diag && col > srow) val = -1e30f;
                pv[c] = val;
                mx = fmaxf(mx, val);
            }
            mx = fmaxf(mx, __shfl_xor_sync(0xffffffffu, mx, 1));
            mx = fmaxf(mx, __shfl_xor_sync(0xffffffffu, mx, 2));
            mx = fmaxf(mx, __shfl_xor_sync(0xffffffffu, mx, 4));
            const float m_old = smf[OFF_M + srow];
            const float m_new = fmaxf(m_old, mx);
            const float corr  = __expf(m_old - m_new);
            float lsum = 0.f;
            #pragma unroll
            for (int c = 0; c < 8; ++c) {
                pv[c] = __expf(pv[c] - m_new);
                lsum += pv[c];
            }
            lsum += __shfl_xor_sync(0xffffffffu, lsum, 1);
            lsum += __shfl_xor_sync(0xffffffffu, lsum, 2);
            lsum += __shfl_xor_sync(0xffffffffu, lsum, 4);
            if ((tid & 7) == 0) {
                smf[OFF_M + srow] = m_new;
                smf[OFF_L + srow] = smf[OFF_L + srow] * corr + lsum;
                smf[OFF_C + srow] = corr;
            }
            __syncwarp();
            const int wbse = OFF_PS + srow * PP + (tid & 7) * 4;
            #pragma unroll
            for (int i = 0; i < 4; ++i) {
                uint32_t H, L;
                packpair(pv[2 * i], pv[2 * i + 1], H, L);
                smu[wbse + i]      = H;
                smu[wbse + 32 + i] = L;
            }
        }
        if (jt < it) CPWAIT1(); else CPWAIT0();   // VT(jt) landed
        __syncthreads();

        // ---- Phase C: acc = acc*corr + P @ V  (vg-interleaved) ----
        {
            const float c_lo = smf[OFF_C + wpm + g];
            const float c_hi = smf[OFF_C + wpm + g + 8];
            #pragma unroll
            for (int nf = 0; nf < 8; ++nf) {
                o[nf][0] *= c_lo; o[nf][1] *= c_lo;
                o[nf][2] *= c_hi; o[nf][3] *= c_hi;
            }
            #pragma unroll
            for (int ks = 0; ks < 4; ++ks) {
                const int wb = ks * 8;
                uint32_t pH[4], pL[4], vHb[2][4], vLb[2][4];
                const uint32_t po = (uint32_t)(rowp * PP + wb + lb4 * 4) * 4;
                ldsm_x4(pH, sb + OFF_PS * 4 + po);
                ldsm_x4(pL, sb + OFF_PS * 4 + po + 128);
#define VLOAD(vg_, bf_) do {                                                \
        const uint32_t _vo = (uint32_t)(                                    \
            (wpn + (vg_) * 16 + lb4 * 8 + l8) * VP + wb + lb3 * 4) * 4;     \
        ldsm_x4(vHb[bf_], sb + OFF_VTH * 4 + _vo);                          \
        ldsm_x4(vLb[bf_], sb + OFF_VTL * 4 + _vo);                          \
    } while (0)
                VLOAD(0, 0);
                #pragma unroll
                for (int vg = 0; vg < 4; ++vg) {
                    const int bf = vg & 1;
                    if (vg < 3) VLOAD(vg + 1, bf ^ 1);
                    MMA_BF16(o[vg * 2],     pH, &vHb[bf][0]);
                    MMA_BF16(o[vg * 2 + 1], pH, &vHb[bf][2]);
                    MMA_BF16(o[vg * 2],     pH, &vLb[bf][0]);
                    MMA_BF16(o[vg * 2 + 1], pH, &vLb[bf][2]);
                    MMA_BF16(o[vg * 2],     pL, &vHb[bf][0]);
                    MMA_BF16(o[vg * 2 + 1], pL, &vHb[bf][2]);
                }
#undef VLOAD
            }
        }
        __syncthreads();    // C done: VT buffer free
        if (jt < it) { ISSUE_VT(jt + 1); CPCOMMIT(); }
    }
#undef ISSUE_K
#undef ISSUE_VT

    // ---- normalize and write packed attn ----
    {
        const float inv_lo = 1.0f / smf[OFF_L + wpm + g];
        const float inv_hi = 1.0f / smf[OFF_L + wpm + g + 8];
        const size_t row_lo = (size_t)(it * 64 + wpm + g);
        const size_t row_hi = row_lo + 8;
        #pragma unroll
        for (int nf = 0; nf < 8; ++nf) {
            const int wcol = h * DKW + (wpn >> 1) + nf * 4 + tig;
            uint32_t H, L;
            packpair(o[nf][0] * inv_lo, o[nf][1] * inv_lo, H, L);
            AHo[row_lo * KW + wcol] = H;
            ALo[row_lo * KW + wcol] = L;
            packpair(o[nf][2] * inv_hi, o[nf][3] * inv_hi, H, L);
            AHo[row_hi * KW + wcol] = H;
            ALo[row_hi * KW + wcol] = L;
        }
    }
}

// ---------------------------------------------------------------------------
extern "C" void kernel_launch(void* const* d_in, const int* in_sizes, int n_in,
                              void* d_out, int out_size)
{
    const float* X   = (const float*)d_in[0];
    const int*   pos = (const int*)  d_in[1];
    const float* wq  = (const float*)d_in[2];
    const float* wk  = (const float*)d_in[3];
    const float* wv  = (const float*)d_in[4];
    const float* wo  = (const float*)d_in[5];
    float* out = (float*)d_out;

    float *q, *kv;
    uint32_t *xH, *xL, *qH, *qL, *kH, *kL, *vtH, *vtL, *aH, *aL;
    uint32_t *wqH, *wqL, *wkvH, *wkvL, *woH, *woL;
    cudaGetSymbolAddress((void**)&q,    g_q);
    cudaGetSymbolAddress((void**)&kv,   g_kv);
    cudaGetSymbolAddress((void**)&xH,   g_xH);   cudaGetSymbolAddress((void**)&xL,   g_xL);
    cudaGetSymbolAddress((void**)&qH,   g_qH);   cudaGetSymbolAddress((void**)&qL,   g_qL);
    cudaGetSymbolAddress((void**)&kH,   g_kH);   cudaGetSymbolAddress((void**)&kL,   g_kL);
    cudaGetSymbolAddress((void**)&vtH,  g_vtH);  cudaGetSymbolAddress((void**)&vtL,  g_vtL);
    cudaGetSymbolAddress((void**)&aH,   g_aH);   cudaGetSymbolAddress((void**)&aL,   g_aL);
    cudaGetSymbolAddress((void**)&wqH,  g_wqH);  cudaGetSymbolAddress((void**)&wqL,  g_wqL);
    cudaGetSymbolAddress((void**)&wkvH, g_wkvH); cudaGetSymbolAddress((void**)&wkvL, g_wkvL);
    cudaGetSymbolAddress((void**)&woH,  g_woH);  cudaGetSymbolAddress((void**)&woL,  g_woL);

    cudaFuncSetAttribute(gemm_presplit,
                         cudaFuncAttributeMaxDynamicSharedMemorySize, GEMM_SMEM);
    cudaFuncSetAttribute(flash_mma_bf16,
                         cudaFuncAttributeMaxDynamicSharedMemorySize, FA3_SMEM);

    dim3 tb(32, 8);
    // weights: K-major hi/lo; wk|wv concatenated into wkv rows 0-255 | 256-511
    transpose_split<<<dim3(HID / 32, HID / 32), tb>>>(wq, wqH, wqL,          // 1
                                                      HID, HID, HID, 0, 0);
    transpose_split<<<dim3(DHD / 32, HID / 32), tb>>>(wk, wkvH, wkvL,        // 2
                                                      HID, DHD, DHD, 0, 0);
    split_rows<<<S_LEN * KW / (256 * 4), 256>>>(X, xH, xL);                  // 3
    gemm_presplit<<<dim3(HID / 128, S_LEN / 128), 256, GEMM_SMEM>>>(         // 4 (ncu)
        xH, xL, wqH, wqL, q, S_LEN, HID, KW);
    transpose_split<<<dim3(DHD / 32, HID / 32), tb>>>(wv, wkvH, wkvL,        // 5
                                                      HID, DHD, DHD, 0, DHD);
    gemm_presplit<<<dim3(512 / 128, S_LEN / 128), 256, GEMM_SMEM>>>(         // 6 fused KV
        xH, xL, wkvH, wkvL, kv, S_LEN, 512, KW);
    rope_split<<<S_LEN, 64>>>(q, kv, pos, qH, qL, kH, kL);                   // 7
    transpose_split<<<dim3(HID / 32, HID / 32), tb>>>(wo, woH, woL,          // 8
                                                      HID, HID, HID, 0, 0);
    transpose_split<<<dim3(DHD / 32, S_LEN / 32), tb>>>(kv, vtH, vtL,        // 9 V^T
                                                        S_LEN, DHD, 512, DHD, 0);
    flash_mma_bf16<<<dim3(S_LEN / 64, NH), 512, FA3_SMEM>>>(                 // 10
        qH, qL, kH, kL, vtH, vtL, aH, aL);
    gemm_presplit<<<dim3(HID / 128, S_LEN / 128), 256, GEMM_SMEM>>>(         // 11
        aH, aL, woH, woL, out, S_LEN, HID, KW);
}

// round 17
// speedup vs baseline: 1.1484x; 1.0300x over previous
#include <cuda_runtime.h>
#include <cuda_bf16.h>
#include <cstdint>

#define S_LEN 4096
#define HID   2048
#define NH    8
#define DHD   256
#define KW    1024      // HID/2 words per row (packed bf16x2)
#define DKW   128       // DHD/2 words
#define SW    2048      // S_LEN/2 words
#define NQKV  2560      // fused q|k|v projection width

// ---------------------------------------------------------------------------
// Scratch (static device globals: allocation-free per harness rules)
// ---------------------------------------------------------------------------
__device__ float    g_qkv[S_LEN * NQKV];                    // fused Q|K|V fp32
__device__ uint32_t g_xH[S_LEN * KW],  g_xL[S_LEN * KW];
__device__ uint32_t g_qH[S_LEN * KW],  g_qL[S_LEN * KW];
__device__ uint32_t g_kH[S_LEN * DKW], g_kL[S_LEN * DKW];
__device__ uint32_t g_vtH[DHD * SW],   g_vtL[DHD * SW];
__device__ uint32_t g_aH[S_LEN * KW],  g_aL[S_LEN * KW];
__device__ uint32_t g_wqkvH[NQKV * KW], g_wqkvL[NQKV * KW]; // wq|wk|wv K-major
__device__ uint32_t g_woH[HID * KW],   g_woL[HID * KW];

// ---------------------------------------------------------------------------
// helpers
// ---------------------------------------------------------------------------
__device__ __forceinline__ uint32_t smem_u32(const void* p) {
    uint32_t a;
    asm("{ .reg .u64 t; cvta.to.shared.u64 t, %1; cvt.u32.u64 %0, t; }"
        : "=r"(a) : "l"(p));
    return a;
}
__device__ __forceinline__ float bf16_rn_f32(float x) {
    return __bfloat162float(__float2bfloat16(x));
}
__device__ __forceinline__ uint32_t bf16pack(float lo_k, float hi_k) {
    uint32_t r;
    asm("cvt.rn.bf16x2.f32 %0, %1, %2;" : "=r"(r) : "f"(hi_k), "f"(lo_k));
    return r;
}
__device__ __forceinline__ void packpair(float a, float b, uint32_t& H, uint32_t& L) {
    H = bf16pack(a, b);
    L = bf16pack(a - bf16_rn_f32(a), b - bf16_rn_f32(b));
}
__device__ __forceinline__ void split_pack4(float4 v, uint32_t* h, uint32_t* l) {
    packpair(v.x, v.y, h[0], l[0]);
    packpair(v.z, v.w, h[1], l[1]);
}
__device__ __forceinline__ void ldsm_x4(uint32_t* r, uint32_t addr) {
    asm volatile("ldmatrix.sync.aligned.m8n8.x4.shared.b16 {%0,%1,%2,%3}, [%4];"
        : "=r"(r[0]), "=r"(r[1]), "=r"(r[2]), "=r"(r[3]) : "r"(addr));
}
#define MMA_BF16(c, a, b)                                                   \
    asm volatile("mma.sync.aligned.m16n8k16.row.col.f32.bf16.bf16.f32 "     \
        "{%0,%1,%2,%3}, {%4,%5,%6,%7}, {%8,%9}, {%0,%1,%2,%3};"             \
        : "+f"((c)[0]), "+f"((c)[1]), "+f"((c)[2]), "+f"((c)[3])            \
        : "r"((a)[0]), "r"((a)[1]), "r"((a)[2]), "r"((a)[3]),               \
          "r"((b)[0]), "r"((b)[1]))
#define CP16(sm, gm) \
    asm volatile("cp.async.cg.shared.global [%0], [%1], 16;" :: "r"(sm), "l"(gm))
#define CPCOMMIT() asm volatile("cp.async.commit_group;")
#define CPWAIT0()  asm volatile("cp.async.wait_group 0;")
#define CPWAIT1()  asm volatile("cp.async.wait_group 1;")

// ---------------------------------------------------------------------------
// split_rows: fp32 [rows][2*Kw] -> packed hi/lo u32 [rows][Kw]
// ---------------------------------------------------------------------------
__global__ void split_rows(const float* __restrict__ in,
                           uint32_t* __restrict__ oH, uint32_t* __restrict__ oL)
{
    const size_t t = (size_t)blockIdx.x * blockDim.x + threadIdx.x;
    const float* p = in + t * 8;
    uint32_t h[2], l[2], h2[2], l2[2];
    split_pack4(*(const float4*)p, h, l);
    split_pack4(*(const float4*)(p + 4), h2, l2);
    *(uint4*)&oH[t * 4] = make_uint4(h[0], h[1], h2[0], h2[1]);
    *(uint4*)&oL[t * 4] = make_uint4(l[0], l[1], l2[0], l2[1]);
}

// ---------------------------------------------------------------------------
// transpose_split: in [R rows][C cols] (row stride ldin, col offset incoff)
//   -> out hi/lo u32 [(outoff + c)][R/2] (pairs along R)
// ---------------------------------------------------------------------------
__global__ void transpose_split(const float* __restrict__ in,
                                uint32_t* __restrict__ oH, uint32_t* __restrict__ oL,
                                int R, int C, int ldin, int incoff, int outoff)
{
    __shared__ float t[32][33];
    const int c0 = blockIdx.x * 32, r0 = blockIdx.y * 32;
    const int tx = threadIdx.x, ty = threadIdx.y;
    #pragma unroll
    for (int j = 0; j < 4; ++j)
        t[ty + 8 * j][tx] = in[(size_t)(r0 + ty + 8 * j) * ldin + incoff + c0 + tx];
    __syncthreads();
    const int Rw = R >> 1;
    #pragma unroll
    for (int j = 0; j < 2; ++j) {
        const int jj = ty + 8 * j;
        const float a = t[2 * jj][tx], b = t[2 * jj + 1][tx];
        uint32_t H, L;
        packpair(a, b, H, L);
        oH[(size_t)(outoff + c0 + tx) * Rw + (r0 >> 1) + jj] = H;
        oL[(size_t)(outoff + c0 + tx) * Rw + (r0 >> 1) + jj] = L;
    }
}

// ---------------------------------------------------------------------------
// rope_split: q from qkv cols 0..2047, k from qkv cols 2048..2303 (stride NQKV)
// ---------------------------------------------------------------------------
__global__ void rope_split(const float* __restrict__ qkv,
                           const int* __restrict__ pos,
                           uint32_t* __restrict__ qH, uint32_t* __restrict__ qL,
                           uint32_t* __restrict__ kH, uint32_t* __restrict__ kL)
{
    const int s = blockIdx.x;
    const int j = threadIdx.x;
    const float p = (float)pos[s];
    const float ia = 1.0f / powf(10000.0f, (float)(2 * j)     * (1.0f / 128.0f));
    const float ib = 1.0f / powf(10000.0f, (float)(2 * j + 1) * (1.0f / 128.0f));
    float sa, ca, sb, cb;
    sincosf(p * ia, &sa, &ca);
    sincosf(p * ib, &sb, &cb);

    #pragma unroll
    for (int h = 0; h < NH; ++h) {
        const float* base = qkv + (size_t)s * NQKV + h * DHD;
        float2 x1 = *(const float2*)&base[2 * j];
        float2 x2 = *(const float2*)&base[128 + 2 * j];
        const size_t wb = (size_t)s * KW + h * DKW;
        uint32_t H, L;
        packpair(x1.x * ca - x2.x * sa, x1.y * cb - x2.y * sb, H, L);
        qH[wb + j] = H;      qL[wb + j] = L;
        packpair(x2.x * ca + x1.x * sa, x2.y * cb + x1.y * sb, H, L);
        qH[wb + 64 + j] = H; qL[wb + 64 + j] = L;
    }
    {
        const float* base = qkv + (size_t)s * NQKV + HID;
        float2 x1 = *(const float2*)&base[2 * j];
        float2 x2 = *(const float2*)&base[128 + 2 * j];
        const size_t wb = (size_t)s * DKW;
        uint32_t H, L;
        packpair(x1.x * ca - x2.x * sa, x1.y * cb - x2.y * sb, H, L);
        kH[wb + j] = H;      kL[wb + j] = L;
        packpair(x2.x * ca + x1.x * sa, x2.y * cb + x1.y * sb, H, L);
        kH[wb + 64 + j] = H; kL[wb + 64 + j] = L;
    }
}

// ---------------------------------------------------------------------------
// GEMM on pre-split inputs (unchanged: 256 thr, 2 CTAs/SM, cp.async dbl-buf).
// ---------------------------------------------------------------------------
#define GP 20
#define OAL_B 10240
#define OBH_B 20480
#define OBL_B 30720
#define BUFW  10240
#define GEMM_SMEM (2 * BUFW * 4)

__global__ __launch_bounds__(256, 2)
void gemm_presplit(const uint32_t* __restrict__ AH, const uint32_t* __restrict__ AL,
                   const uint32_t* __restrict__ BH, const uint32_t* __restrict__ BL,
                   float* __restrict__ C, int M, int N, int Kw)
{
    extern __shared__ uint32_t smu[];
    const uint32_t sb = smem_u32(smu);

    const int tid  = threadIdx.x;
    const int wid  = tid >> 5, lane = tid & 31;
    const int g    = lane >> 2, tig = lane & 3;
    const int l8   = lane & 7, lb3 = (lane >> 3) & 1, lb4 = (lane >> 4) & 1;
    const int wm   = (wid & 1) * 64;
    const int wn   = (wid >> 1) * 32;
    const int m0   = blockIdx.y * 128, n0 = blockIdx.x * 128;

    const int lr = tid >> 1;
    const int wc = (tid & 1) * 8;
    const uint32_t* gah = AH + (size_t)(m0 + lr) * Kw + wc;
    const uint32_t* gal = AL + (size_t)(m0 + lr) * Kw + wc;
    const uint32_t* gbh = BH + (size_t)(n0 + lr) * Kw + wc;
    const uint32_t* gbl = BL + (size_t)(n0 + lr) * Kw + wc;

#define GISSUE(ci, bufbyte) do {                                            \
        const uint32_t _b = sb + (bufbyte) + (lr * GP + wc) * 4;            \
        const uint32_t* _g;                                                 \
        _g = gah + (ci) * 16; CP16(_b,         _g); CP16(_b + 16,         _g + 4); \
        _g = gal + (ci) * 16; CP16(_b + OAL_B, _g); CP16(_b + OAL_B + 16, _g + 4); \
        _g = gbh + (ci) * 16; CP16(_b + OBH_B, _g); CP16(_b + OBH_B + 16, _g + 4); \
        _g = gbl + (ci) * 16; CP16(_b + OBL_B, _g); CP16(_b + OBL_B + 16, _g + 4); \
    } while (0)

    float c[16][4];
    #pragma unroll
    for (int i = 0; i < 16; ++i)
        #pragma unroll
        for (int j = 0; j < 4; ++j) c[i][j] = 0.f;

    const int nch = Kw / 16;
    GISSUE(0, 0);
    CPCOMMIT();

    for (int c0 = 0; c0 < nch; ++c0) {
        const uint32_t cb = (uint32_t)(c0 & 1) * (BUFW * 4);
        if (c0 + 1 < nch) {
            GISSUE(c0 + 1, (uint32_t)((c0 + 1) & 1) * (BUFW * 4));
            CPCOMMIT();
            CPWAIT1();
        } else {
            CPWAIT0();
        }
        __syncthreads();

        #pragma unroll
        for (int ks = 0; ks < 2; ++ks) {
            const int wb = ks * 8;
            uint32_t aH[4][4], bH[2][4], bL[2][4];
            #pragma unroll
            for (int mt = 0; mt < 4; ++mt) {
                const uint32_t ro = (uint32_t)((wm + mt * 16 + l8 + lb3 * 8) * GP
                                               + wb + lb4 * 4) * 4;
                ldsm_x4(aH[mt], sb + cb + ro);
            }
            #pragma unroll
            for (int p = 0; p < 2; ++p) {
                const uint32_t ro = (uint32_t)((wn + p * 16 + lb4 * 8 + l8) * GP
                                               + wb + lb3 * 4) * 4;
                ldsm_x4(bH[p], sb + cb + OBH_B + ro);
                ldsm_x4(bL[p], sb + cb + OBL_B + ro);
            }
            #pragma unroll
            for (int mt = 0; mt < 4; ++mt)
                #pragma unroll
                for (int nt = 0; nt < 4; ++nt)
                    MMA_BF16(c[mt * 4 + nt], aH[mt], &bH[nt >> 1][(nt & 1) * 2]);
            #pragma unroll
            for (int mt = 0; mt < 4; ++mt)
                #pragma unroll
                for (int nt = 0; nt < 4; ++nt)
                    MMA_BF16(c[mt * 4 + nt], aH[mt], &bL[nt >> 1][(nt & 1) * 2]);
            uint32_t aL[4][4];
            #pragma unroll
            for (int mt = 0; mt < 4; ++mt) {
                const uint32_t ro = (uint32_t)((wm + mt * 16 + l8 + lb3 * 8) * GP
                                               + wb + lb4 * 4) * 4;
                ldsm_x4(aL[mt], sb + cb + OAL_B + ro);
            }
            #pragma unroll
            for (int mt = 0; mt < 4; ++mt)
                #pragma unroll
                for (int nt = 0; nt < 4; ++nt)
                    MMA_BF16(c[mt * 4 + nt], aL[mt], &bH[nt >> 1][(nt & 1) * 2]);
        }
        __syncthreads();
    }
#undef GISSUE

    #pragma unroll
    for (int mt = 0; mt < 4; ++mt)
        #pragma unroll
        for (int nt = 0; nt < 4; ++nt) {
            const float* cc = c[mt * 4 + nt];
            const int row = m0 + wm + mt * 16 + g;
            const int col = n0 + wn + nt * 8 + 2 * tig;
            *(float2*)&C[(size_t)row * N + col]       = make_float2(cc[0], cc[1]);
            *(float2*)&C[(size_t)(row + 8) * N + col] = make_float2(cc[2], cc[3]);
        }
}

// ---------------------------------------------------------------------------
// Flash attention, 512 threads; skewed cp.async.
// Phase A: 8 warps, 4m x 2n (16x32 tile)  — halves Q fragment duplication.
// Phase C: 16 warps, 2m x 8n (32x32 tile) — halves V fragment duplication.
// ---------------------------------------------------------------------------
#define QP 132
#define VP 36
#define PP 68
#define OFF_QH 0
#define OFF_QL (OFF_QH + 64 * QP)
#define OFF_KH (OFF_QL + 64 * QP)
#define OFF_KL (OFF_KH + 64 * QP)
#define OFF_VTH (OFF_KL + 64 * QP)
#define OFF_VTL (OFF_VTH + 256 * VP)
#define OFF_PS  (OFF_VTL + 256 * VP)
#define OFF_M   (OFF_PS + 64 * PP)
#define OFF_L   (OFF_M + 64)
#define OFF_C   (OFF_L + 64)
#define FA3_SMEM ((OFF_C + 64) * 4)

__global__ __launch_bounds__(512, 1) void flash_mma_bf16(
    const uint32_t* __restrict__ Qh, const uint32_t* __restrict__ Ql,
    const uint32_t* __restrict__ Kh, const uint32_t* __restrict__ Kl,
    const uint32_t* __restrict__ VtH, const uint32_t* __restrict__ VtL,
    uint32_t* __restrict__ AHo, uint32_t* __restrict__ ALo)
{
    extern __shared__ uint32_t smu[];
    float* smf = (float*)smu;
    const uint32_t sb = smem_u32(smu);

    const int tid  = threadIdx.x;
    const int wid  = tid >> 5, lane = tid & 31;
    const int g    = lane >> 2, tig = lane & 3;
    const int l8   = lane & 7, lb3 = (lane >> 3) & 1, lb4 = (lane >> 4) & 1;
    const int h    = blockIdx.y;
    const int it   = gridDim.x - 1 - blockIdx.x;

    // Phase A (warps 0-7): 4m x 2n, warp tile 16 rows x 32 cols
    const int wqm = (wid & 3) * 16;
    const int wqn = (wid >> 2) * 32;
    // Phase C (all 16 warps): 2m x 8n, warp tile 32 rows x 32 dims
    const int wpm = (wid & 1) * 32;
    const int wpn = (wid >> 1) * 32;

    const int lr = tid & 63, lq = (tid >> 6) * 16;
    const int vd = tid >> 1, vh = (tid & 1) * 16;
    const int srow = tid >> 3, sseg = (tid & 7) * 8;

#define ISSUE_K(jt_) do {                                                   \
        const uint32_t* _sH = Kh + (size_t)((jt_) * 64 + lr) * DKW + lq;    \
        const uint32_t* _sL = Kl + (size_t)((jt_) * 64 + lr) * DKW + lq;    \
        const uint32_t _dh = sb + (uint32_t)(OFF_KH + lr * QP + lq) * 4;    \
        const uint32_t _dl = sb + (uint32_t)(OFF_KL + lr * QP + lq) * 4;    \
        CP16(_dh, _sH); CP16(_dh + 16, _sH + 4);                            \
        CP16(_dh + 32, _sH + 8); CP16(_dh + 48, _sH + 12);                  \
        CP16(_dl, _sL); CP16(_dl + 16, _sL + 4);                            \
        CP16(_dl + 32, _sL + 8); CP16(_dl + 48, _sL + 12);                  \
    } while (0)

#define ISSUE_VT(jt_) do {                                                  \
        const uint32_t* _sH = VtH + (size_t)vd * SW + (jt_) * 32 + vh;      \
        const uint32_t* _sL = VtL + (size_t)vd * SW + (jt_) * 32 + vh;      \
        const uint32_t _dh = sb + (uint32_t)(OFF_VTH + vd * VP + vh) * 4;   \
        const uint32_t _dl = sb + (uint32_t)(OFF_VTL + vd * VP + vh) * 4;   \
        CP16(_dh, _sH); CP16(_dh + 16, _sH + 4);                            \
        CP16(_dh + 32, _sH + 8); CP16(_dh + 48, _sH + 12);                  \
        CP16(_dl, _sL); CP16(_dl + 16, _sL + 4);                            \
        CP16(_dl + 32, _sL + 8); CP16(_dl + 48, _sL + 12);                  \
    } while (0)

    ISSUE_K(0);  CPCOMMIT();
    ISSUE_VT(0); CPCOMMIT();

    // ---- stage Q + init state (overlaps prologue cp.async) ----
    {
        const uint32_t* sH = Qh + (size_t)(it * 64 + lr) * KW + h * DKW + lq;
        const uint32_t* sL = Ql + (size_t)(it * 64 + lr) * KW + h * DKW + lq;
        const int d = lr * QP + lq;
        #pragma unroll
        for (int i = 0; i < 4; ++i) {
            *(uint4*)&smu[OFF_QH + d + 4 * i] = *(const uint4*)(sH + 4 * i);
            *(uint4*)&smu[OFF_QL + d + 4 * i] = *(const uint4*)(sL + 4 * i);
        }
        if (tid < 64) { smf[OFF_M + tid] = -1e30f; smf[OFF_L + tid] = 0.f; }
    }

    float o[2][4][4];
    #pragma unroll
    for (int m = 0; m < 2; ++m)
        #pragma unroll
        for (int n = 0; n < 4; ++n)
            #pragma unroll
            for (int j = 0; j < 4; ++j) o[m][n][j] = 0.f;

    const int rowq  = wqm + l8 + lb3 * 8;
    const uint32_t kfrag_base = (lb4 ? OFF_KL : OFF_KH) * 4;

    for (int jt = 0; jt <= it; ++jt) {
        CPWAIT1();          // K(jt) landed (VT(jt) may still be in flight)
        __syncthreads();

        // ---- Phase A (warps 0-7): S = Q K^T ----
        if (wid < 8) {
            float s[4][4];
            #pragma unroll
            for (int a = 0; a < 4; ++a)
                #pragma unroll
                for (int j = 0; j < 4; ++j) s[a][j] = 0.f;

            #pragma unroll 4
            for (int ks = 0; ks < 16; ++ks) {
                const int wb = ks * 8;
                uint32_t fH[4], fL[4], b[4][4];
                const uint32_t qo = (uint32_t)(rowq * QP + wb + lb4 * 4) * 4;
                ldsm_x4(fH, sb + OFF_QH * 4 + qo);
                ldsm_x4(fL, sb + OFF_QL * 4 + qo);
                #pragma unroll
                for (int j = 0; j < 4; ++j) {
                    const int rowk = wqn + j * 8 + l8;
                    ldsm_x4(b[j], sb + kfrag_base
                                   + (uint32_t)(rowk * QP + wb + lb3 * 4) * 4);
                }
                #pragma unroll
                for (int j = 0; j < 4; ++j) MMA_BF16(s[j], fH, &b[j][0]);  // hh
                #pragma unroll
                for (int j = 0; j < 4; ++j) MMA_BF16(s[j], fH, &b[j][2]);  // hl
                #pragma unroll
                for (int j = 0; j < 4; ++j) MMA_BF16(s[j], fL, &b[j][0]);  // lh
            }
            #pragma unroll
            for (int j = 0; j < 4; ++j) {
                const int row = wqm + g;
                const int col = wqn + j * 8 + 2 * tig;
                *(float2*)&smf[OFF_PS + row * PP + col]       = make_float2(s[j][0], s[j][1]);
                *(float2*)&smf[OFF_PS + (row + 8) * PP + col] = make_float2(s[j][2], s[j][3]);
            }
        }
        __syncthreads();    // A done: PS complete, K buffer free

        if (jt < it) { ISSUE_K(jt + 1); CPCOMMIT(); }

        // ---- Phase B: online softmax; pack P in place ----
        {
            const bool diag = (jt == it);
            float pv[8];
            float mx = -1e30f;
            #pragma unroll
            for (int c = 0; c < 8; ++c) {
                const int col = sseg + c;
                float val = smf[OFF_PS + srow * PP + col] * 0.0625f;
                if (diag && col > srow) val = -1e30f;
                pv[c] = val;
                mx = fmaxf(mx, val);
            }
            mx = fmaxf(mx, __shfl_xor_sync(0xffffffffu, mx, 1));
            mx = fmaxf(mx, __shfl_xor_sync(0xffffffffu, mx, 2));
            mx = fmaxf(mx, __shfl_xor_sync(0xffffffffu, mx, 4));
            const float m_old = smf[OFF_M + srow];
            const float m_new = fmaxf(m_old, mx);
            const float corr  = __expf(m_old - m_new);
            float lsum = 0.f;
            #pragma unroll
            for (int c = 0; c < 8; ++c) {
                pv[c] = __expf(pv[c] - m_new);
                lsum += pv[c];
            }
            lsum += __shfl_xor_sync(0xffffffffu, lsum, 1);
            lsum += __shfl_xor_sync(0xffffffffu, lsum, 2);
            lsum += __shfl_xor_sync(0xffffffffu, lsum, 4);
            if ((tid & 7) == 0) {
                smf[OFF_M + srow] = m_new;
                smf[OFF_L + srow] = smf[OFF_L + srow] * corr + lsum;
                smf[OFF_C + srow] = corr;
            }
            __syncwarp();
            const int wbse = OFF_PS + srow * PP + (tid & 7) * 4;
            #pragma unroll
            for (int i = 0; i < 4; ++i) {
                uint32_t H, L;
                packpair(pv[2 * i], pv[2 * i + 1], H, L);
                smu[wbse + i]      = H;
                smu[wbse + 32 + i] = L;
            }
        }
        if (jt < it) CPWAIT1(); else CPWAIT0();   // VT(jt) landed
        __syncthreads();

        // ---- Phase C: acc = acc*corr + P @ V  (2m x 8n map) ----
        {
            float cf[4];
            cf[0] = smf[OFF_C + wpm + g];
            cf[1] = smf[OFF_C + wpm + 8 + g];
            cf[2] = smf[OFF_C + wpm + 16 + g];
            cf[3] = smf[OFF_C + wpm + 24 + g];
            #pragma unroll
            for (int m = 0; m < 2; ++m)
                #pragma unroll
                for (int n = 0; n < 4; ++n) {
                    o[m][n][0] *= cf[2 * m];     o[m][n][1] *= cf[2 * m];
                    o[m][n][2] *= cf[2 * m + 1]; o[m][n][3] *= cf[2 * m + 1];
                }
            #pragma unroll
            for (int ks = 0; ks < 4; ++ks) {
                const int wb = ks * 8;
                uint32_t pH[2][4], pL[2][4], vH[2][4], vL[2][4];
                #pragma unroll
                for (int m = 0; m < 2; ++m) {
                    const int rowp = wpm + m * 16 + l8 + lb3 * 8;
                    const uint32_t po = (uint32_t)(rowp * PP + wb + lb4 * 4) * 4;
                    ldsm_x4(pH[m], sb + OFF_PS * 4 + po);
                    ldsm_x4(pL[m], sb + OFF_PS * 4 + po + 128);
                }
                #pragma unroll
                for (int q = 0; q < 2; ++q) {
                    const uint32_t vo = (uint32_t)(
                        (wpn + q * 16 + lb4 * 8 + l8) * VP + wb + lb3 * 4) * 4;
                    ldsm_x4(vH[q], sb + OFF_VTH * 4 + vo);
                    ldsm_x4(vL[q], sb + OFF_VTL * 4 + vo);
                }
                #pragma unroll
                for (int m = 0; m < 2; ++m)
                    #pragma unroll
                    for (int n = 0; n < 4; ++n)
                        MMA_BF16(o[m][n], pH[m], &vH[n >> 1][(n & 1) * 2]);  // hh
                #pragma unroll
                for (int m = 0; m < 2; ++m)
                    #pragma unroll
                    for (int n = 0; n < 4; ++n)
                        MMA_BF16(o[m][n], pH[m], &vL[n >> 1][(n & 1) * 2]);  // hl
                #pragma unroll
                for (int m = 0; m < 2; ++m)
                    #pragma unroll
                    for (int n = 0; n < 4; ++n)
                        MMA_BF16(o[m][n], pL[m], &vH[n >> 1][(n & 1) * 2]);  // lh
            }
        }
        __syncthreads();    // C done: VT buffer free
        if (jt < it) { ISSUE_VT(jt + 1); CPCOMMIT(); }
    }
#undef ISSUE_K
#undef ISSUE_VT

    // ---- normalize and write packed attn ----
    {
        float inv[4];
        inv[0] = 1.0f / smf[OFF_L + wpm + g];
        inv[1] = 1.0f / smf[OFF_L + wpm + 8 + g];
        inv[2] = 1.0f / smf[OFF_L + wpm + 16 + g];
        inv[3] = 1.0f / smf[OFF_L + wpm + 24 + g];
        #pragma unroll
        for (int m = 0; m < 2; ++m)
            #pragma unroll
            for (int n = 0; n < 4; ++n) {
                const size_t row_lo = (size_t)(it * 64 + wpm + m * 16 + g);
                const size_t row_hi = row_lo + 8;
                const int wcol = h * DKW + (wpn >> 1) + n * 4 + tig;
                uint32_t H, L;
                packpair(o[m][n][0] * inv[2 * m], o[m][n][1] * inv[2 * m], H, L);
                AHo[row_lo * KW + wcol] = H;
                ALo[row_lo * KW + wcol] = L;
                packpair(o[m][n][2] * inv[2 * m + 1], o[m][n][3] * inv[2 * m + 1], H, L);
                AHo[row_hi * KW + wcol] = H;
                ALo[row_hi * KW + wcol] = L;
            }
    }
}

// ---------------------------------------------------------------------------
extern "C" void kernel_launch(void* const* d_in, const int* in_sizes, int n_in,
                              void* d_out, int out_size)
{
    const float* X   = (const float*)d_in[0];
    const int*   pos = (const int*)  d_in[1];
    const float* wq  = (const float*)d_in[2];
    const float* wk  = (const float*)d_in[3];
    const float* wv  = (const float*)d_in[4];
    const float* wo  = (const float*)d_in[5];
    float* out = (float*)d_out;

    float *qkv;
    uint32_t *xH, *xL, *qH, *qL, *kH, *kL, *vtH, *vtL, *aH, *aL;
    uint32_t *wqkvH, *wqkvL, *woH, *woL;
    cudaGetSymbolAddress((void**)&qkv,   g_qkv);
    cudaGetSymbolAddress((void**)&xH,    g_xH);    cudaGetSymbolAddress((void**)&xL,    g_xL);
    cudaGetSymbolAddress((void**)&qH,    g_qH);    cudaGetSymbolAddress((void**)&qL,    g_qL);
    cudaGetSymbolAddress((void**)&kH,    g_kH);    cudaGetSymbolAddress((void**)&kL,    g_kL);
    cudaGetSymbolAddress((void**)&vtH,   g_vtH);   cudaGetSymbolAddress((void**)&vtL,   g_vtL);
    cudaGetSymbolAddress((void**)&aH,    g_aH);    cudaGetSymbolAddress((void**)&aL,    g_aL);
    cudaGetSymbolAddress((void**)&wqkvH, g_wqkvH); cudaGetSymbolAddress((void**)&wqkvL, g_wqkvL);
    cudaGetSymbolAddress((void**)&woH,   g_woH);   cudaGetSymbolAddress((void**)&woL,   g_woL);

    cudaFuncSetAttribute(gemm_presplit,
                         cudaFuncAttributeMaxDynamicSharedMemorySize, GEMM_SMEM);
    cudaFuncSetAttribute(flash_mma_bf16,
                         cudaFuncAttributeMaxDynamicSharedMemorySize, FA3_SMEM);

    dim3 tb(32, 8);
    // fused weight: rows 0-2047 = wq^T, 2048-2303 = wk^T, 2304-2559 = wv^T
    transpose_split<<<dim3(HID / 32, HID / 32), tb>>>(wq, wqkvH, wqkvL,      // 1
                                                      HID, HID, HID, 0, 0);
    transpose_split<<<dim3(DHD / 32, HID / 32), tb>>>(wk, wqkvH, wqkvL,      // 2
                                                      HID, DHD, DHD, 0, HID);
    transpose_split<<<dim3(DHD / 32, HID / 32), tb>>>(wv, wqkvH, wqkvL,      // 3
                                                      HID, DHD, DHD, 0, HID + DHD);
    split_rows<<<S_LEN * KW / (256 * 4), 256>>>(X, xH, xL);                  // 4
    gemm_presplit<<<dim3(NQKV / 128, S_LEN / 128), 256, GEMM_SMEM>>>(        // 5 fused QKV
        xH, xL, wqkvH, wqkvL, qkv, S_LEN, NQKV, KW);
    rope_split<<<S_LEN, 64>>>(qkv, pos, qH, qL, kH, kL);                     // 6
    transpose_split<<<dim3(HID / 32, HID / 32), tb>>>(wo, woH, woL,          // 7
                                                      HID, HID, HID, 0, 0);
    transpose_split<<<dim3(DHD / 32, S_LEN / 32), tb>>>(qkv, vtH, vtL,       // 8 V^T
                                                        S_LEN, DHD, NQKV, HID + DHD, 0);
    flash_mma_bf16<<<dim3(S_LEN / 64, NH), 512, FA3_SMEM>>>(                 // 9
        qH, qL, kH, kL, vtH, vtL, aH, aL);
    gemm_presplit<<<dim3(HID / 128, S_LEN / 128), 256, GEMM_SMEM>>>(         // 10
        aH, aL, woH, woL, out, S_LEN, HID, KW);
}